// round 5
// baseline (speedup 1.0000x reference)
#include <cuda_runtime.h>
#include <cuda_bf16.h>
#include <cstdint>
#include <math.h>

#define T_   2048
#define HS_  4096
#define NH_  32
#define NKV_ 8
#define HD_  128
#define QKVN_ ((NH_ + 2*NKV_)*HD_)   // 6144

// ======================= helpers ===========================================
__device__ __forceinline__ uint32_t smem_to_u32(const void* smem_ptr) {
    uint32_t addr;
    asm("{ .reg .u64 tmp; cvta.to.shared.u64 tmp, %1; cvt.u32.u64 %0, tmp; }"
        : "=r"(addr) : "l"(smem_ptr));
    return addr;
}
__device__ __forceinline__ void ldsm_x4(uint32_t addr, uint32_t* r) {
    asm volatile("ldmatrix.sync.aligned.m8n8.x4.shared.b16 {%0,%1,%2,%3}, [%4];"
        : "=r"(r[0]), "=r"(r[1]), "=r"(r[2]), "=r"(r[3]) : "r"(addr));
}
__device__ __forceinline__ void ldsm_x4_trans(uint32_t addr, uint32_t* r) {
    asm volatile("ldmatrix.sync.aligned.m8n8.x4.trans.shared.b16 {%0,%1,%2,%3}, [%4];"
        : "=r"(r[0]), "=r"(r[1]), "=r"(r[2]), "=r"(r[3]) : "r"(addr));
}
__device__ __forceinline__ void mma16816(float* d, const uint32_t* a,
                                         const uint32_t b0, const uint32_t b1) {
    asm volatile("mma.sync.aligned.m16n8k16.row.col.f32.bf16.bf16.f32 "
        "{%0,%1,%2,%3}, {%4,%5,%6,%7}, {%8,%9}, {%0,%1,%2,%3};"
        : "+f"(d[0]), "+f"(d[1]), "+f"(d[2]), "+f"(d[3])
        : "r"(a[0]), "r"(a[1]), "r"(a[2]), "r"(a[3]), "r"(b0), "r"(b1));
}
__device__ __forceinline__ uint32_t pack_bf16(float a, float b) {
    __nv_bfloat162 t = __floats2bfloat162_rn(a, b);
    return *reinterpret_cast<uint32_t*>(&t);
}
__device__ __forceinline__ void split2(float a, float b,
                                       uint32_t& hi, uint32_t& lo) {
    __nv_bfloat16 ha = __float2bfloat16(a), hb = __float2bfloat16(b);
    hi = pack_bf16(__bfloat162float(ha), __bfloat162float(hb));
    lo = pack_bf16(a - __bfloat162float(ha), b - __bfloat162float(hb));
}

// ======================= scratch (device globals) ===========================
__device__ __align__(256) __nv_bfloat16 g_xnh[T_*HS_];
__device__ __align__(256) __nv_bfloat16 g_xnl[T_*HS_];
__device__ __align__(256) __nv_bfloat16 g_wqh[QKVN_*HS_];
__device__ __align__(256) __nv_bfloat16 g_wql[QKVN_*HS_];
__device__ __align__(256) __nv_bfloat16 g_woh[HS_*HS_];
__device__ __align__(256) __nv_bfloat16 g_wol[HS_*HS_];
__device__ __align__(256) __nv_bfloat16 g_atth[T_*HS_];
__device__ __align__(256) __nv_bfloat16 g_attl[T_*HS_];
__device__ float g_qkv[T_*QKVN_];
__device__ __align__(256) __nv_bfloat16 g_qh[NH_ *T_*HD_];
__device__ __align__(256) __nv_bfloat16 g_ql[NH_ *T_*HD_];
__device__ __align__(256) __nv_bfloat16 g_kh[NKV_*T_*HD_];
__device__ __align__(256) __nv_bfloat16 g_kl[NKV_*T_*HD_];
__device__ __align__(256) __nv_bfloat16 g_vh[NKV_*T_*HD_];
__device__ __align__(256) __nv_bfloat16 g_vl[NKV_*T_*HD_];

// ======================= kernel: fp32 -> (hi,lo) bf16 split =================
__global__ void cvt_split_kernel(const float* __restrict__ x,
                                 __nv_bfloat16* __restrict__ h,
                                 __nv_bfloat16* __restrict__ l, int n) {
    int i = (blockIdx.x * blockDim.x + threadIdx.x) * 4;
    if (i >= n) return;
    float4 v = *(const float4*)(x + i);
    __nv_bfloat16 h0 = __float2bfloat16(v.x);
    __nv_bfloat16 h1 = __float2bfloat16(v.y);
    __nv_bfloat16 h2 = __float2bfloat16(v.z);
    __nv_bfloat16 h3 = __float2bfloat16(v.w);
    __nv_bfloat162* hp = (__nv_bfloat162*)(h + i);
    __nv_bfloat162* lp = (__nv_bfloat162*)(l + i);
    hp[0] = __nv_bfloat162(h0, h1);
    hp[1] = __nv_bfloat162(h2, h3);
    lp[0] = __nv_bfloat162(__float2bfloat16(v.x - __bfloat162float(h0)),
                           __float2bfloat16(v.y - __bfloat162float(h1)));
    lp[1] = __nv_bfloat162(__float2bfloat16(v.z - __bfloat162float(h2)),
                           __float2bfloat16(v.w - __bfloat162float(h3)));
}

// ======================= kernel: RMSNorm(hidden) -> hi/lo bf16 ==============
__global__ void rmsnorm_x_kernel(const float* __restrict__ x,
                                 const float* __restrict__ w) {
    int row = blockIdx.x;
    const float* xr = x + (size_t)row * HS_;
    float ss = 0.f;
    for (int i = threadIdx.x; i < HS_; i += blockDim.x) {
        float v = xr[i];
        ss += v * v;
    }
    for (int off = 16; off; off >>= 1)
        ss += __shfl_xor_sync(0xffffffffu, ss, off);
    __shared__ float wr[8];
    int lane = threadIdx.x & 31, wid = threadIdx.x >> 5;
    if (lane == 0) wr[wid] = ss;
    __syncthreads();
    float tot = 0.f;
#pragma unroll
    for (int i = 0; i < 8; i++) tot += wr[i];
    float inv = rsqrtf(tot / (float)HS_ + 1e-6f);
    for (int i = threadIdx.x; i < HS_; i += blockDim.x) {
        float v = xr[i] * inv * w[i];
        __nv_bfloat16 h = __float2bfloat16(v);
        g_xnh[(size_t)row * HS_ + i] = h;
        g_xnl[(size_t)row * HS_ + i] = __float2bfloat16(v - __bfloat162float(h));
    }
}

// ======================= bf16 split GEMM: C = A*B^T (+bias) =================
// 512 threads, 16 warps (4x4), CTA 128x128, warp tile 32x32, 3-stage pipeline.
#define BM 128
#define BN 128
#define BK 32
#define ROWB 80                  // bytes per smem row: 40 bf16 (pad 32->40)
#define ARR  (128 * ROWB)        // 10240 bytes per array
#define STG  (4 * ARR)           // Ah, Al, Bh, Bl per stage = 40960
#define GEMM_SMEM (3 * STG)      // 122880 (3-stage pipeline)

__device__ __forceinline__ void gemm_load_stage(
    uint32_t sb, int stage,
    const __nv_bfloat16* __restrict__ Ah, const __nv_bfloat16* __restrict__ Al,
    const __nv_bfloat16* __restrict__ Bh, const __nv_bfloat16* __restrict__ Bl,
    int bm, int bn, int k0, int K, int tid)
{
    uint32_t base = sb + stage * STG;
#pragma unroll
    for (int s = tid; s < 2048; s += 512) {
        int arr = s >> 9;
        int rc = s & 511;
        int r = rc >> 2, c = rc & 3;
        const __nv_bfloat16* srcb =
            (arr == 0) ? Ah : (arr == 1) ? Al : (arr == 2) ? Bh : Bl;
        int grow = ((arr < 2) ? bm : bn) + r;
        const __nv_bfloat16* src = srcb + (size_t)grow * K + k0 + c * 8;
        uint32_t dst = base + arr * ARR + r * ROWB + c * 16;
        asm volatile("cp.async.cg.shared.global [%0], [%1], 16;"
                     :: "r"(dst), "l"(src));
    }
    asm volatile("cp.async.commit_group;" ::: "memory");
}

__global__ void __launch_bounds__(512, 1)
gemm_bf16x3_kernel(const __nv_bfloat16* __restrict__ Ah,
                   const __nv_bfloat16* __restrict__ Al,
                   const __nv_bfloat16* __restrict__ Bh,
                   const __nv_bfloat16* __restrict__ Bl,
                   const float* __restrict__ bias,
                   float* __restrict__ C, int N, int K)
{
    extern __shared__ char smem[];
    uint32_t sb = smem_to_u32(smem);
    int tid = threadIdx.x, lane = tid & 31, wid = tid >> 5;
    int wm = wid >> 2, wn = wid & 3;       // warp grid 4 x 4
    int bm = blockIdx.y * BM, bn = blockIdx.x * BN;
    int nk = K / BK;

    float acc[2][4][4];
#pragma unroll
    for (int i = 0; i < 2; i++)
#pragma unroll
        for (int j = 0; j < 4; j++)
#pragma unroll
            for (int c = 0; c < 4; c++) acc[i][j][c] = 0.f;

    gemm_load_stage(sb, 0, Ah, Al, Bh, Bl, bm, bn, 0,      K, tid);
    gemm_load_stage(sb, 1, Ah, Al, Bh, Bl, bm, bn, BK,     K, tid);
    gemm_load_stage(sb, 2, Ah, Al, Bh, Bl, bm, bn, 2 * BK, K, tid);

    int a_r = (lane & 15);
    int a_c8 = (lane >> 4) << 3;
    int b_r = (lane & 7) + ((lane & 16) >> 1);
    int b_c8 = (lane & 8);

    for (int it = 0; it < nk; it++) {
        asm volatile("cp.async.wait_group 2;" ::: "memory");
        __syncthreads();

        uint32_t ab  = sb + (it % 3) * STG;
        uint32_t alb = ab + ARR;
        uint32_t bhb = ab + 2 * ARR;
        uint32_t blb = ab + 3 * ARR;

#pragma unroll
        for (int ks = 0; ks < BK; ks += 16) {
            int acolB = (ks + a_c8) * 2;
            int bcolB = (ks + b_c8) * 2;
            uint32_t bh[2][4], bl[2][4];
#pragma unroll
            for (int g = 0; g < 2; g++) {
                uint32_t ro = (uint32_t)((wn * 32 + g * 16 + b_r) * ROWB);
                ldsm_x4(bhb + ro + bcolB, bh[g]);
                ldsm_x4(blb + ro + bcolB, bl[g]);
            }
#pragma unroll
            for (int mi = 0; mi < 2; mi++) {
                uint32_t ah[4], al[4];
                uint32_t ro = (uint32_t)((wm * 32 + mi * 16 + a_r) * ROWB);
                ldsm_x4(ab  + ro + acolB, ah);
                ldsm_x4(alb + ro + acolB, al);
#pragma unroll
                for (int g = 0; g < 2; g++) {
                    mma16816(acc[mi][2*g],   ah, bh[g][0], bh[g][1]);
                    mma16816(acc[mi][2*g],   ah, bl[g][0], bl[g][1]);
                    mma16816(acc[mi][2*g],   al, bh[g][0], bh[g][1]);
                    mma16816(acc[mi][2*g+1], ah, bh[g][2], bh[g][3]);
                    mma16816(acc[mi][2*g+1], ah, bl[g][2], bl[g][3]);
                    mma16816(acc[mi][2*g+1], al, bh[g][2], bh[g][3]);
                }
            }
        }
        __syncthreads();
        if (it + 3 < nk)
            gemm_load_stage(sb, it % 3, Ah, Al, Bh, Bl, bm, bn,
                            (it + 3) * BK, K, tid);
    }

#pragma unroll
    for (int mi = 0; mi < 2; mi++) {
#pragma unroll
        for (int j = 0; j < 4; j++) {
            int r0 = bm + wm * 32 + mi * 16 + (lane >> 2);
            int c0 = bn + wn * 32 + j * 8 + 2 * (lane & 3);
            float b0 = 0.f, b1 = 0.f;
            if (bias) { b0 = bias[c0]; b1 = bias[c0 + 1]; }
            float2 v0 = make_float2(acc[mi][j][0] + b0, acc[mi][j][1] + b1);
            float2 v1 = make_float2(acc[mi][j][2] + b0, acc[mi][j][3] + b1);
            *(float2*)(C + (size_t)r0 * N + c0) = v0;
            *(float2*)(C + (size_t)(r0 + 8) * N + c0) = v1;
        }
    }
}

// ======================= kernel: per-head RMSNorm + RoPE -> hi/lo ===========
__global__ void qk_rope_kernel(const int* __restrict__ positions,
                               const float* __restrict__ qw,
                               const float* __restrict__ kw) {
    int t = blockIdx.x;
    int head = blockIdx.y;
    int i = threadIdx.x;   // 0..127
    float v = g_qkv[(size_t)t * QKVN_ + head * HD_ + i];

    if (head >= NH_ + NKV_) {   // v heads: split into hi/lo [KV,T,D]
        size_t idx = ((size_t)(head - NH_ - NKV_) * T_ + t) * HD_ + i;
        __nv_bfloat16 h = __float2bfloat16(v);
        g_vh[idx] = h;
        g_vl[idx] = __float2bfloat16(v - __bfloat162float(h));
        return;
    }

    float ss = v * v;
    for (int off = 16; off; off >>= 1)
        ss += __shfl_xor_sync(0xffffffffu, ss, off);
    __shared__ float wr[4];
    __shared__ float buf[HD_];
    int lane = i & 31, wid = i >> 5;
    if (lane == 0) wr[wid] = ss;
    __syncthreads();
    float tot = wr[0] + wr[1] + wr[2] + wr[3];
    float inv = rsqrtf(tot / (float)HD_ + 1e-6f);
    const float* w = (head < NH_) ? qw : kw;
    float nv = v * inv * w[i];
    buf[i] = nv;
    __syncthreads();

    int fi = i & 63;
    float invf = 1.0f / powf(10000.0f, (float)fi * (1.0f / 64.0f));
    float ang = (float)positions[t] * invf;
    float s, c;
    sincosf(ang, &s, &c);
    float other = buf[i ^ 64];
    float out = (i < 64) ? (nv * c - other * s) : (nv * c + other * s);

    if (head < NH_) {
        float sc = out * 0.08838834764831845f;   // fold in softmax scale
        size_t idx = ((size_t)head * T_ + t) * HD_ + i;
        __nv_bfloat16 h = __float2bfloat16(sc);
        g_qh[idx] = h;
        g_ql[idx] = __float2bfloat16(sc - __bfloat162float(h));
    } else {
        size_t idx = ((size_t)(head - NH_) * T_ + t) * HD_ + i;
        __nv_bfloat16 h = __float2bfloat16(out);
        g_kh[idx] = h;
        g_kl[idx] = __float2bfloat16(out - __bfloat162float(h));
    }
}

// ======================= tensor-core flash attention ========================
#define ASTR 272                    // smem row stride bytes (136 bf16)
#define AQSZ (128 * ASTR)           // 34816: one Q array (128 rows)
#define AKSZ (64 * ASTR)            // 17408: one K/V array (64 rows)
#define ASTAGE (4 * AKSZ)           // 69632: Kh,Kl,Vh,Vl
#define ATT_SMEM (2 * AQSZ + 2 * ASTAGE)   // 208896

__device__ __forceinline__ void attn_load_kv(
    uint32_t sb, int buf,
    const __nv_bfloat16* Kh, const __nv_bfloat16* Kl,
    const __nv_bfloat16* Vh, const __nv_bfloat16* Vl,
    int kt0, int tid)
{
    uint32_t base = sb + 2 * AQSZ + buf * ASTAGE;
#pragma unroll
    for (int ii = 0; ii < 16; ii++) {
        int s = tid + ii * 256;
        int arr = s >> 10;          // 0..3
        int r = (s >> 4) & 63;
        int c = s & 15;
        const __nv_bfloat16* src =
            (arr == 0) ? Kh : (arr == 1) ? Kl : (arr == 2) ? Vh : Vl;
        src += (size_t)(kt0 + r) * HD_ + c * 8;
        uint32_t dst = base + arr * AKSZ + r * ASTR + c * 16;
        asm volatile("cp.async.cg.shared.global [%0], [%1], 16;"
                     :: "r"(dst), "l"(src));
    }
    asm volatile("cp.async.commit_group;" ::: "memory");
}

__global__ void __launch_bounds__(256, 1) attn_mma_kernel() {
    extern __shared__ char smc[];
    uint32_t sb = smem_to_u32(smc);
    int qb = 15 - blockIdx.x;            // reversed: big workloads first
    int h  = blockIdx.y;
    int kvh = h >> 2;
    int tid = threadIdx.x, lane = tid & 31, wid = tid >> 5;

    const __nv_bfloat16* Qhg = g_qh + ((size_t)h * T_ + qb * 128) * HD_;
    const __nv_bfloat16* Qlg = g_ql + ((size_t)h * T_ + qb * 128) * HD_;
    const __nv_bfloat16* Khg = g_kh + (size_t)kvh * T_ * HD_;
    const __nv_bfloat16* Klg = g_kl + (size_t)kvh * T_ * HD_;
    const __nv_bfloat16* Vhg = g_vh + (size_t)kvh * T_ * HD_;
    const __nv_bfloat16* Vlg = g_vl + (size_t)kvh * T_ * HD_;

    // Q load (group 1)
#pragma unroll
    for (int ii = 0; ii < 16; ii++) {
        int s = tid + ii * 256;
        int arr = s >> 11;              // 0 = hi, 1 = lo
        int r = (s >> 4) & 127;
        int c = s & 15;
        const __nv_bfloat16* src = (arr ? Qlg : Qhg) + (size_t)r * HD_ + c * 8;
        uint32_t dst = sb + arr * AQSZ + r * ASTR + c * 16;
        asm volatile("cp.async.cg.shared.global [%0], [%1], 16;"
                     :: "r"(dst), "l"(src));
    }
    asm volatile("cp.async.commit_group;" ::: "memory");

    int nkt = 2 * qb + 2;
    attn_load_kv(sb, 0, Khg, Klg, Vhg, Vlg, 0,  tid);
    attn_load_kv(sb, 1, Khg, Klg, Vhg, Vlg, 64, tid);

    asm volatile("cp.async.wait_group 2;" ::: "memory");   // Q done
    __syncthreads();

    // extract Q fragments to registers
    int a_r = lane & 15, a_c8 = (lane >> 4) << 3;
    uint32_t qhf[8][4], qlf[8][4];
    {
        uint32_t qrow = (uint32_t)((wid * 16 + a_r) * ASTR);
#pragma unroll
        for (int j = 0; j < 8; j++) {
            uint32_t co = (uint32_t)((j * 16 + a_c8) * 2);
            ldsm_x4(sb + qrow + co, qhf[j]);
            ldsm_x4(sb + AQSZ + qrow + co, qlf[j]);
        }
    }

    float o[16][4];
#pragma unroll
    for (int j = 0; j < 16; j++)
#pragma unroll
        for (int c = 0; c < 4; c++) o[j][c] = 0.f;
    float mA = -1e30f, mB = -1e30f, lA = 0.f, lB = 0.f;

    int b_r = (lane & 7) + ((lane & 16) >> 1);   // K frag row map
    int b_c8 = (lane & 8);
    int v_r = (lane & 7) + 8 * ((lane >> 3) & 1);  // V trans frag row map
    int v_c8 = (lane >> 4) * 8;

    int wrow = qb * 128 + wid * 16;              // warp's first q row

    for (int kb = 0; kb < nkt; kb++) {
        asm volatile("cp.async.wait_group 1;" ::: "memory");
        __syncthreads();

        int kbase = kb * 64;
        bool active = (kbase <= wrow + 15);      // any unmasked element?
        uint32_t st = sb + 2 * AQSZ + (kb & 1) * ASTAGE;

        if (active) {
            // ---- S = Q K^T (split x3) ----
            float s[8][4];
#pragma unroll
            for (int t = 0; t < 8; t++)
#pragma unroll
                for (int c = 0; c < 4; c++) s[t][c] = 0.f;

#pragma unroll
            for (int j = 0; j < 8; j++) {        // k16 over D
                uint32_t colB = (uint32_t)((j * 16 + b_c8) * 2);
#pragma unroll
                for (int g = 0; g < 4; g++) {    // n16 over 64 tokens
                    uint32_t kh[4], kl[4];
                    uint32_t ro = st + (uint32_t)((g * 16 + b_r) * ASTR) + colB;
                    ldsm_x4(ro, kh);
                    ldsm_x4(ro + AKSZ, kl);
                    mma16816(s[2*g],   qhf[j], kh[0], kh[1]);
                    mma16816(s[2*g],   qhf[j], kl[0], kl[1]);
                    mma16816(s[2*g],   qlf[j], kh[0], kh[1]);
                    mma16816(s[2*g+1], qhf[j], kh[2], kh[3]);
                    mma16816(s[2*g+1], qhf[j], kl[2], kl[3]);
                    mma16816(s[2*g+1], qlf[j], kh[2], kh[3]);
                }
            }

            // ---- causal mask (diagonal tiles only) ----
            if (kbase + 63 > wrow) {
                int rA = wrow + (lane >> 2), rB = rA + 8;
#pragma unroll
                for (int t = 0; t < 8; t++) {
                    int c0 = kbase + t * 8 + 2 * (lane & 3);
                    if (c0     > rA) s[t][0] = -1e30f;
                    if (c0 + 1 > rA) s[t][1] = -1e30f;
                    if (c0     > rB) s[t][2] = -1e30f;
                    if (c0 + 1 > rB) s[t][3] = -1e30f;
                }
            }

            // ---- online softmax ----
            float rmA = -1e30f, rmB = -1e30f;
#pragma unroll
            for (int t = 0; t < 8; t++) {
                rmA = fmaxf(rmA, fmaxf(s[t][0], s[t][1]));
                rmB = fmaxf(rmB, fmaxf(s[t][2], s[t][3]));
            }
            rmA = fmaxf(rmA, __shfl_xor_sync(0xffffffffu, rmA, 1));
            rmA = fmaxf(rmA, __shfl_xor_sync(0xffffffffu, rmA, 2));
            rmB = fmaxf(rmB, __shfl_xor_sync(0xffffffffu, rmB, 1));
            rmB = fmaxf(rmB, __shfl_xor_sync(0xffffffffu, rmB, 2));
            float mnA = fmaxf(mA, rmA), mnB = fmaxf(mB, rmB);
            float aA = __expf(mA - mnA), aB = __expf(mB - mnB);
            mA = mnA; mB = mnB;

            float rsA = 0.f, rsB = 0.f;
#pragma unroll
            for (int t = 0; t < 8; t++) {
                s[t][0] = __expf(s[t][0] - mnA);
                s[t][1] = __expf(s[t][1] - mnA);
                s[t][2] = __expf(s[t][2] - mnB);
                s[t][3] = __expf(s[t][3] - mnB);
                rsA += s[t][0] + s[t][1];
                rsB += s[t][2] + s[t][3];
            }
            rsA += __shfl_xor_sync(0xffffffffu, rsA, 1);
            rsA += __shfl_xor_sync(0xffffffffu, rsA, 2);
            rsB += __shfl_xor_sync(0xffffffffu, rsB, 1);
            rsB += __shfl_xor_sync(0xffffffffu, rsB, 2);
            lA = lA * aA + rsA;
            lB = lB * aB + rsB;
#pragma unroll
            for (int j = 0; j < 16; j++) {
                o[j][0] *= aA; o[j][1] *= aA;
                o[j][2] *= aB; o[j][3] *= aB;
            }

            // ---- O += P V (split x3) ----
#pragma unroll
            for (int t = 0; t < 4; t++) {        // k16 over 64 tokens
                uint32_t pah[4], pal[4];
                split2(s[2*t][0],   s[2*t][1],   pah[0], pal[0]);
                split2(s[2*t][2],   s[2*t][3],   pah[1], pal[1]);
                split2(s[2*t+1][0], s[2*t+1][1], pah[2], pal[2]);
                split2(s[2*t+1][2], s[2*t+1][3], pah[3], pal[3]);
                uint32_t vrow = st + 2 * AKSZ
                              + (uint32_t)((t * 16 + v_r) * ASTR);
#pragma unroll
                for (int g = 0; g < 8; g++) {    // n16 over D
                    uint32_t vh[4], vl[4];
                    uint32_t vo = vrow + (uint32_t)((g * 16 + v_c8) * 2);
                    ldsm_x4_trans(vo, vh);
                    ldsm_x4_trans(vo + AKSZ, vl);
                    mma16816(o[2*g],   pah, vh[0], vh[1]);
                    mma16816(o[2*g],   pah, vl[0], vl[1]);
                    mma16816(o[2*g],   pal, vh[0], vh[1]);
                    mma16816(o[2*g+1], pah, vh[2], vh[3]);
                    mma16816(o[2*g+1], pah, vl[2], vl[3]);
                    mma16816(o[2*g+1], pal, vh[2], vh[3]);
                }
            }
        }

        __syncthreads();
        if (kb + 2 < nkt)
            attn_load_kv(sb, kb & 1, Khg, Klg, Vhg, Vlg, (kb + 2) * 64, tid);
    }

    // ---- epilogue: normalize, split to hi/lo bf16 ----
    float ilA = 1.f / lA, ilB = 1.f / lB;
    int rowA = wrow + (lane >> 2);
#pragma unroll
    for (int j = 0; j < 16; j++) {
        int col = h * HD_ + j * 8 + 2 * (lane & 3);
        float v0 = o[j][0] * ilA, v1 = o[j][1] * ilA;
        float v2 = o[j][2] * ilB, v3 = o[j][3] * ilB;
        uint32_t hA, lAo, hB, lBo;
        split2(v0, v1, hA, lAo);
        split2(v2, v3, hB, lBo);
        *(uint32_t*)(g_atth + (size_t)rowA * HS_ + col) = hA;
        *(uint32_t*)(g_attl + (size_t)rowA * HS_ + col) = lAo;
        *(uint32_t*)(g_atth + (size_t)(rowA + 8) * HS_ + col) = hB;
        *(uint32_t*)(g_attl + (size_t)(rowA + 8) * HS_ + col) = lBo;
    }
}

// ======================= launcher ===========================================
extern "C" void kernel_launch(void* const* d_in, const int* in_sizes, int n_in,
                              void* d_out, int out_size) {
    const int*   positions = (const int*)d_in[0];
    const float* hidden    = (const float*)d_in[1];
    const float* ln_w      = (const float*)d_in[2];
    const float* qkv_w     = (const float*)d_in[3];
    const float* qkv_b     = (const float*)d_in[4];
    const float* qn_w      = (const float*)d_in[5];
    const float* kn_w      = (const float*)d_in[6];
    const float* o_w       = (const float*)d_in[7];
    float* out = (float*)d_out;

    void* p;
    cudaGetSymbolAddress(&p, g_xnh);  __nv_bfloat16* xnh = (__nv_bfloat16*)p;
    cudaGetSymbolAddress(&p, g_xnl);  __nv_bfloat16* xnl = (__nv_bfloat16*)p;
    cudaGetSymbolAddress(&p, g_wqh);  __nv_bfloat16* wqh = (__nv_bfloat16*)p;
    cudaGetSymbolAddress(&p, g_wql);  __nv_bfloat16* wql = (__nv_bfloat16*)p;
    cudaGetSymbolAddress(&p, g_woh);  __nv_bfloat16* woh = (__nv_bfloat16*)p;
    cudaGetSymbolAddress(&p, g_wol);  __nv_bfloat16* wol = (__nv_bfloat16*)p;
    cudaGetSymbolAddress(&p, g_atth); __nv_bfloat16* ath = (__nv_bfloat16*)p;
    cudaGetSymbolAddress(&p, g_attl); __nv_bfloat16* atl = (__nv_bfloat16*)p;
    cudaGetSymbolAddress(&p, g_qkv);  float* qkv = (float*)p;

    // weight splits (hi/lo)
    {
        int n1 = QKVN_ * HS_;
        cvt_split_kernel<<<n1 / 4 / 256, 256>>>(qkv_w, wqh, wql, n1);
        int n2 = HS_ * HS_;
        cvt_split_kernel<<<n2 / 4 / 256, 256>>>(o_w, woh, wol, n2);
    }

    // 1) RMSNorm(hidden) -> hi/lo
    rmsnorm_x_kernel<<<T_, 256>>>(hidden, ln_w);

    // 2) qkv = xn @ qkv_w^T + bias   (HMMA, split-bf16 x3, 16 warps)
    cudaFuncSetAttribute(gemm_bf16x3_kernel,
                         cudaFuncAttributeMaxDynamicSharedMemorySize, GEMM_SMEM);
    gemm_bf16x3_kernel<<<dim3(QKVN_ / BN, T_ / BM), 512, GEMM_SMEM>>>(
        xnh, xnl, wqh, wql, qkv_b, qkv, QKVN_, HS_);

    // 3) q/k RMSNorm + RoPE (scale folded into q), v split
    qk_rope_kernel<<<dim3(T_, NH_ + 2 * NKV_), 128>>>(positions, qn_w, kn_w);

    // 4) causal attention (tensor-core flash, split-bf16 x3)
    cudaFuncSetAttribute(attn_mma_kernel,
                         cudaFuncAttributeMaxDynamicSharedMemorySize, ATT_SMEM);
    attn_mma_kernel<<<dim3(T_ / 128, NH_), 256, ATT_SMEM>>>();

    // 5) out = att @ o_w^T  (HMMA, split-bf16 x3, 16 warps)
    gemm_bf16x3_kernel<<<dim3(HS_ / BN, T_ / BM), 512, GEMM_SMEM>>>(
        ath, atl, woh, wol, nullptr, out, HS_, HS_);
}

// round 6
// speedup vs baseline: 1.1425x; 1.1425x over previous
#include <cuda_runtime.h>
#include <cuda_bf16.h>
#include <cstdint>
#include <math.h>

#define T_   2048
#define HS_  4096
#define NH_  32
#define NKV_ 8
#define HD_  128
#define QKVN_ ((NH_ + 2*NKV_)*HD_)   // 6144

// ======================= helpers ===========================================
__device__ __forceinline__ uint32_t smem_to_u32(const void* smem_ptr) {
    uint32_t addr;
    asm("{ .reg .u64 tmp; cvta.to.shared.u64 tmp, %1; cvt.u32.u64 %0, tmp; }"
        : "=r"(addr) : "l"(smem_ptr));
    return addr;
}
__device__ __forceinline__ void ldsm_x4(uint32_t addr, uint32_t* r) {
    asm volatile("ldmatrix.sync.aligned.m8n8.x4.shared.b16 {%0,%1,%2,%3}, [%4];"
        : "=r"(r[0]), "=r"(r[1]), "=r"(r[2]), "=r"(r[3]) : "r"(addr));
}
__device__ __forceinline__ void ldsm_x4_trans(uint32_t addr, uint32_t* r) {
    asm volatile("ldmatrix.sync.aligned.m8n8.x4.trans.shared.b16 {%0,%1,%2,%3}, [%4];"
        : "=r"(r[0]), "=r"(r[1]), "=r"(r[2]), "=r"(r[3]) : "r"(addr));
}
__device__ __forceinline__ void mma16816(float* d, const uint32_t* a,
                                         const uint32_t b0, const uint32_t b1) {
    asm volatile("mma.sync.aligned.m16n8k16.row.col.f32.bf16.bf16.f32 "
        "{%0,%1,%2,%3}, {%4,%5,%6,%7}, {%8,%9}, {%0,%1,%2,%3};"
        : "+f"(d[0]), "+f"(d[1]), "+f"(d[2]), "+f"(d[3])
        : "r"(a[0]), "r"(a[1]), "r"(a[2]), "r"(a[3]), "r"(b0), "r"(b1));
}
__device__ __forceinline__ uint32_t pack_bf16(float a, float b) {
    __nv_bfloat162 t = __floats2bfloat162_rn(a, b);
    return *reinterpret_cast<uint32_t*>(&t);
}
__device__ __forceinline__ void split2(float a, float b,
                                       uint32_t& hi, uint32_t& lo) {
    __nv_bfloat16 ha = __float2bfloat16(a), hb = __float2bfloat16(b);
    hi = pack_bf16(__bfloat162float(ha), __bfloat162float(hb));
    lo = pack_bf16(a - __bfloat162float(ha), b - __bfloat162float(hb));
}

// ======================= scratch (device globals) ===========================
__device__ __align__(256) __nv_bfloat16 g_xnh[T_*HS_];
__device__ __align__(256) __nv_bfloat16 g_xnl[T_*HS_];
__device__ __align__(256) __nv_bfloat16 g_wqh[QKVN_*HS_];
__device__ __align__(256) __nv_bfloat16 g_wql[QKVN_*HS_];
__device__ __align__(256) __nv_bfloat16 g_woh[HS_*HS_];
__device__ __align__(256) __nv_bfloat16 g_wol[HS_*HS_];
__device__ __align__(256) __nv_bfloat16 g_atth[T_*HS_];
__device__ __align__(256) __nv_bfloat16 g_attl[T_*HS_];
__device__ float g_qkv[T_*QKVN_];
__device__ __align__(256) __nv_bfloat16 g_qh[NH_ *T_*HD_];
__device__ __align__(256) __nv_bfloat16 g_ql[NH_ *T_*HD_];
__device__ __align__(256) __nv_bfloat16 g_kh[NKV_*T_*HD_];
__device__ __align__(256) __nv_bfloat16 g_kl[NKV_*T_*HD_];
__device__ __align__(256) __nv_bfloat16 g_vh[NKV_*T_*HD_];
__device__ __align__(256) __nv_bfloat16 g_vl[NKV_*T_*HD_];

// ======================= kernel: fp32 -> (hi,lo) bf16 split =================
__global__ void cvt_split_kernel(const float* __restrict__ x,
                                 __nv_bfloat16* __restrict__ h,
                                 __nv_bfloat16* __restrict__ l, int n) {
    int i = (blockIdx.x * blockDim.x + threadIdx.x) * 4;
    if (i >= n) return;
    float4 v = *(const float4*)(x + i);
    __nv_bfloat16 h0 = __float2bfloat16(v.x);
    __nv_bfloat16 h1 = __float2bfloat16(v.y);
    __nv_bfloat16 h2 = __float2bfloat16(v.z);
    __nv_bfloat16 h3 = __float2bfloat16(v.w);
    __nv_bfloat162* hp = (__nv_bfloat162*)(h + i);
    __nv_bfloat162* lp = (__nv_bfloat162*)(l + i);
    hp[0] = __nv_bfloat162(h0, h1);
    hp[1] = __nv_bfloat162(h2, h3);
    lp[0] = __nv_bfloat162(__float2bfloat16(v.x - __bfloat162float(h0)),
                           __float2bfloat16(v.y - __bfloat162float(h1)));
    lp[1] = __nv_bfloat162(__float2bfloat16(v.z - __bfloat162float(h2)),
                           __float2bfloat16(v.w - __bfloat162float(h3)));
}

// ======================= kernel: RMSNorm(hidden) -> hi/lo bf16 ==============
__global__ void rmsnorm_x_kernel(const float* __restrict__ x,
                                 const float* __restrict__ w) {
    int row = blockIdx.x;
    const float* xr = x + (size_t)row * HS_;
    float ss = 0.f;
    for (int i = threadIdx.x; i < HS_; i += blockDim.x) {
        float v = xr[i];
        ss += v * v;
    }
    for (int off = 16; off; off >>= 1)
        ss += __shfl_xor_sync(0xffffffffu, ss, off);
    __shared__ float wr[8];
    int lane = threadIdx.x & 31, wid = threadIdx.x >> 5;
    if (lane == 0) wr[wid] = ss;
    __syncthreads();
    float tot = 0.f;
#pragma unroll
    for (int i = 0; i < 8; i++) tot += wr[i];
    float inv = rsqrtf(tot / (float)HS_ + 1e-6f);
    for (int i = threadIdx.x; i < HS_; i += blockDim.x) {
        float v = xr[i] * inv * w[i];
        __nv_bfloat16 h = __float2bfloat16(v);
        g_xnh[(size_t)row * HS_ + i] = h;
        g_xnl[(size_t)row * HS_ + i] = __float2bfloat16(v - __bfloat162float(h));
    }
}

// ======================= bf16 split GEMM: C = A*B^T (+bias) =================
// 256 threads, 8 warps (2x4), CTA 128x256, warp tile 64x64, 3-stage pipeline.
// Per warp-k16-step: 16 LDSM : 96 MMA  (tensor-bound, not LDS-bound).
#define BM 128
#define BN 256
#define BK 32
#define ROWB 80                  // bytes per smem row: 40 bf16 (pad 32->40)
#define A_ARR (128 * ROWB)       // 10240 per A array
#define B_ARR (256 * ROWB)       // 20480 per B array
#define AL_OFF A_ARR
#define BH_OFF (2 * A_ARR)
#define BL_OFF (2 * A_ARR + B_ARR)
#define STG  (2 * A_ARR + 2 * B_ARR)   // 61440 bytes per stage
#define GEMM_SMEM (3 * STG)            // 184320

__device__ __forceinline__ void gemm_load_stage(
    uint32_t sb, int stage,
    const __nv_bfloat16* __restrict__ Ah, const __nv_bfloat16* __restrict__ Al,
    const __nv_bfloat16* __restrict__ Bh, const __nv_bfloat16* __restrict__ Bl,
    int bm, int bn, int k0, int K, int tid)
{
    uint32_t base = sb + stage * STG;
    // A: 2 arrays x 128 rows x 4 chunks = 1024; B: 2 x 256 x 4 = 2048; total 3072
#pragma unroll
    for (int ii = 0; ii < 12; ii++) {
        int s = tid + ii * 256;
        const __nv_bfloat16* src;
        uint32_t dst;
        if (s < 1024) {
            int arr = s >> 9;            // 0=Ah 1=Al
            int r = (s >> 2) & 127, c = s & 3;
            src = (arr ? Al : Ah) + (size_t)(bm + r) * K + k0 + c * 8;
            dst = base + arr * A_ARR + r * ROWB + c * 16;
        } else {
            int t = s - 1024;
            int arr = t >> 10;           // 0=Bh 1=Bl
            int r = (t >> 2) & 255, c = t & 3;
            src = (arr ? Bl : Bh) + (size_t)(bn + r) * K + k0 + c * 8;
            dst = base + BH_OFF + arr * B_ARR + r * ROWB + c * 16;
        }
        asm volatile("cp.async.cg.shared.global [%0], [%1], 16;"
                     :: "r"(dst), "l"(src));
    }
    asm volatile("cp.async.commit_group;" ::: "memory");
}

__global__ void __launch_bounds__(256, 1)
gemm_bf16x3_kernel(const __nv_bfloat16* __restrict__ Ah,
                   const __nv_bfloat16* __restrict__ Al,
                   const __nv_bfloat16* __restrict__ Bh,
                   const __nv_bfloat16* __restrict__ Bl,
                   const float* __restrict__ bias,
                   float* __restrict__ C, int N, int K)
{
    extern __shared__ char smem[];
    uint32_t sb = smem_to_u32(smem);
    int tid = threadIdx.x, lane = tid & 31, wid = tid >> 5;
    int wm = wid >> 2, wn = wid & 3;       // warp grid 2 x 4
    int bm = blockIdx.y * BM, bn = blockIdx.x * BN;
    int nk = K / BK;

    float acc[4][8][4];
#pragma unroll
    for (int i = 0; i < 4; i++)
#pragma unroll
        for (int j = 0; j < 8; j++)
#pragma unroll
            for (int c = 0; c < 4; c++) acc[i][j][c] = 0.f;

    gemm_load_stage(sb, 0, Ah, Al, Bh, Bl, bm, bn, 0,      K, tid);
    gemm_load_stage(sb, 1, Ah, Al, Bh, Bl, bm, bn, BK,     K, tid);
    gemm_load_stage(sb, 2, Ah, Al, Bh, Bl, bm, bn, 2 * BK, K, tid);

    int a_r = (lane & 15);
    int a_c8 = (lane >> 4) << 3;
    int b_r = (lane & 7) + ((lane & 16) >> 1);
    int b_c8 = (lane & 8);

    for (int it = 0; it < nk; it++) {
        asm volatile("cp.async.wait_group 2;" ::: "memory");
        __syncthreads();

        uint32_t base = sb + (it % 3) * STG;

#pragma unroll
        for (int ks = 0; ks < BK; ks += 16) {
            int acolB = (ks + a_c8) * 2;
            int bcolB = (ks + b_c8) * 2;
            uint32_t bh[4][4], bl[4][4];
#pragma unroll
            for (int g = 0; g < 4; g++) {
                uint32_t ro = (uint32_t)((wn * 64 + g * 16 + b_r) * ROWB) + bcolB;
                ldsm_x4(base + BH_OFF + ro, bh[g]);
                ldsm_x4(base + BL_OFF + ro, bl[g]);
            }
#pragma unroll
            for (int mi = 0; mi < 4; mi++) {
                uint32_t ah[4], al[4];
                uint32_t ro = (uint32_t)((wm * 64 + mi * 16 + a_r) * ROWB) + acolB;
                ldsm_x4(base + ro, ah);
                ldsm_x4(base + AL_OFF + ro, al);
#pragma unroll
                for (int g = 0; g < 4; g++) {
                    mma16816(acc[mi][2*g],   ah, bh[g][0], bh[g][1]);
                    mma16816(acc[mi][2*g],   ah, bl[g][0], bl[g][1]);
                    mma16816(acc[mi][2*g],   al, bh[g][0], bh[g][1]);
                    mma16816(acc[mi][2*g+1], ah, bh[g][2], bh[g][3]);
                    mma16816(acc[mi][2*g+1], ah, bl[g][2], bl[g][3]);
                    mma16816(acc[mi][2*g+1], al, bh[g][2], bh[g][3]);
                }
            }
        }
        __syncthreads();
        if (it + 3 < nk)
            gemm_load_stage(sb, it % 3, Ah, Al, Bh, Bl, bm, bn,
                            (it + 3) * BK, K, tid);
    }

#pragma unroll
    for (int mi = 0; mi < 4; mi++) {
#pragma unroll
        for (int j = 0; j < 8; j++) {
            int r0 = bm + wm * 64 + mi * 16 + (lane >> 2);
            int c0 = bn + wn * 64 + j * 8 + 2 * (lane & 3);
            float b0 = 0.f, b1 = 0.f;
            if (bias) { b0 = bias[c0]; b1 = bias[c0 + 1]; }
            float2 v0 = make_float2(acc[mi][j][0] + b0, acc[mi][j][1] + b1);
            float2 v1 = make_float2(acc[mi][j][2] + b0, acc[mi][j][3] + b1);
            *(float2*)(C + (size_t)r0 * N + c0) = v0;
            *(float2*)(C + (size_t)(r0 + 8) * N + c0) = v1;
        }
    }
}

// ======================= kernel: per-head RMSNorm + RoPE -> hi/lo ===========
__global__ void qk_rope_kernel(const int* __restrict__ positions,
                               const float* __restrict__ qw,
                               const float* __restrict__ kw) {
    int t = blockIdx.x;
    int head = blockIdx.y;
    int i = threadIdx.x;   // 0..127
    float v = g_qkv[(size_t)t * QKVN_ + head * HD_ + i];

    if (head >= NH_ + NKV_) {   // v heads: split into hi/lo [KV,T,D]
        size_t idx = ((size_t)(head - NH_ - NKV_) * T_ + t) * HD_ + i;
        __nv_bfloat16 h = __float2bfloat16(v);
        g_vh[idx] = h;
        g_vl[idx] = __float2bfloat16(v - __bfloat162float(h));
        return;
    }

    float ss = v * v;
    for (int off = 16; off; off >>= 1)
        ss += __shfl_xor_sync(0xffffffffu, ss, off);
    __shared__ float wr[4];
    __shared__ float buf[HD_];
    int lane = i & 31, wid = i >> 5;
    if (lane == 0) wr[wid] = ss;
    __syncthreads();
    float tot = wr[0] + wr[1] + wr[2] + wr[3];
    float inv = rsqrtf(tot / (float)HD_ + 1e-6f);
    const float* w = (head < NH_) ? qw : kw;
    float nv = v * inv * w[i];
    buf[i] = nv;
    __syncthreads();

    int fi = i & 63;
    float invf = 1.0f / powf(10000.0f, (float)fi * (1.0f / 64.0f));
    float ang = (float)positions[t] * invf;
    float s, c;
    sincosf(ang, &s, &c);
    float other = buf[i ^ 64];
    float out = (i < 64) ? (nv * c - other * s) : (nv * c + other * s);

    if (head < NH_) {
        float sc = out * 0.08838834764831845f;   // fold in softmax scale
        size_t idx = ((size_t)head * T_ + t) * HD_ + i;
        __nv_bfloat16 h = __float2bfloat16(sc);
        g_qh[idx] = h;
        g_ql[idx] = __float2bfloat16(sc - __bfloat162float(h));
    } else {
        size_t idx = ((size_t)(head - NH_) * T_ + t) * HD_ + i;
        __nv_bfloat16 h = __float2bfloat16(out);
        g_kh[idx] = h;
        g_kl[idx] = __float2bfloat16(out - __bfloat162float(h));
    }
}

// ======================= tensor-core flash attention ========================
#define ASTR 272                    // smem row stride bytes (136 bf16)
#define AQSZ (128 * ASTR)           // 34816: one Q array (128 rows)
#define AKSZ (64 * ASTR)            // 17408: one K/V array (64 rows)
#define ASTAGE (4 * AKSZ)           // 69632: Kh,Kl,Vh,Vl
#define ATT_SMEM (2 * AQSZ + 2 * ASTAGE)   // 208896

__device__ __forceinline__ void attn_load_kv(
    uint32_t sb, int buf,
    const __nv_bfloat16* Kh, const __nv_bfloat16* Kl,
    const __nv_bfloat16* Vh, const __nv_bfloat16* Vl,
    int kt0, int tid)
{
    uint32_t base = sb + 2 * AQSZ + buf * ASTAGE;
#pragma unroll
    for (int ii = 0; ii < 16; ii++) {
        int s = tid + ii * 256;
        int arr = s >> 10;          // 0..3
        int r = (s >> 4) & 63;
        int c = s & 15;
        const __nv_bfloat16* src =
            (arr == 0) ? Kh : (arr == 1) ? Kl : (arr == 2) ? Vh : Vl;
        src += (size_t)(kt0 + r) * HD_ + c * 8;
        uint32_t dst = base + arr * AKSZ + r * ASTR + c * 16;
        asm volatile("cp.async.cg.shared.global [%0], [%1], 16;"
                     :: "r"(dst), "l"(src));
    }
    asm volatile("cp.async.commit_group;" ::: "memory");
}

__global__ void __launch_bounds__(256, 1) attn_mma_kernel() {
    extern __shared__ char smc[];
    uint32_t sb = smem_to_u32(smc);
    int qb = 15 - blockIdx.x;            // reversed: big workloads first
    int h  = blockIdx.y;
    int kvh = h >> 2;
    int tid = threadIdx.x, lane = tid & 31, wid = tid >> 5;

    const __nv_bfloat16* Qhg = g_qh + ((size_t)h * T_ + qb * 128) * HD_;
    const __nv_bfloat16* Qlg = g_ql + ((size_t)h * T_ + qb * 128) * HD_;
    const __nv_bfloat16* Khg = g_kh + (size_t)kvh * T_ * HD_;
    const __nv_bfloat16* Klg = g_kl + (size_t)kvh * T_ * HD_;
    const __nv_bfloat16* Vhg = g_vh + (size_t)kvh * T_ * HD_;
    const __nv_bfloat16* Vlg = g_vl + (size_t)kvh * T_ * HD_;

    // Q load (group 1)
#pragma unroll
    for (int ii = 0; ii < 16; ii++) {
        int s = tid + ii * 256;
        int arr = s >> 11;              // 0 = hi, 1 = lo
        int r = (s >> 4) & 127;
        int c = s & 15;
        const __nv_bfloat16* src = (arr ? Qlg : Qhg) + (size_t)r * HD_ + c * 8;
        uint32_t dst = sb + arr * AQSZ + r * ASTR + c * 16;
        asm volatile("cp.async.cg.shared.global [%0], [%1], 16;"
                     :: "r"(dst), "l"(src));
    }
    asm volatile("cp.async.commit_group;" ::: "memory");

    int nkt = 2 * qb + 2;
    attn_load_kv(sb, 0, Khg, Klg, Vhg, Vlg, 0,  tid);
    attn_load_kv(sb, 1, Khg, Klg, Vhg, Vlg, 64, tid);

    asm volatile("cp.async.wait_group 2;" ::: "memory");   // Q done
    __syncthreads();

    // extract Q fragments to registers
    int a_r = lane & 15, a_c8 = (lane >> 4) << 3;
    uint32_t qhf[8][4], qlf[8][4];
    {
        uint32_t qrow = (uint32_t)((wid * 16 + a_r) * ASTR);
#pragma unroll
        for (int j = 0; j < 8; j++) {
            uint32_t co = (uint32_t)((j * 16 + a_c8) * 2);
            ldsm_x4(sb + qrow + co, qhf[j]);
            ldsm_x4(sb + AQSZ + qrow + co, qlf[j]);
        }
    }

    float o[16][4];
#pragma unroll
    for (int j = 0; j < 16; j++)
#pragma unroll
        for (int c = 0; c < 4; c++) o[j][c] = 0.f;
    float mA = -1e30f, mB = -1e30f, lA = 0.f, lB = 0.f;

    int b_r = (lane & 7) + ((lane & 16) >> 1);   // K frag row map
    int b_c8 = (lane & 8);
    int v_r = (lane & 7) + 8 * ((lane >> 3) & 1);  // V trans frag row map
    int v_c8 = (lane >> 4) * 8;

    int wrow = qb * 128 + wid * 16;              // warp's first q row

    for (int kb = 0; kb < nkt; kb++) {
        asm volatile("cp.async.wait_group 1;" ::: "memory");
        __syncthreads();

        int kbase = kb * 64;
        bool active = (kbase <= wrow + 15);      // any unmasked element?
        uint32_t st = sb + 2 * AQSZ + (kb & 1) * ASTAGE;

        if (active) {
            // ---- S = Q K^T (split x3) ----
            float s[8][4];
#pragma unroll
            for (int t = 0; t < 8; t++)
#pragma unroll
                for (int c = 0; c < 4; c++) s[t][c] = 0.f;

#pragma unroll
            for (int j = 0; j < 8; j++) {        // k16 over D
                uint32_t colB = (uint32_t)((j * 16 + b_c8) * 2);
#pragma unroll
                for (int g = 0; g < 4; g++) {    // n16 over 64 tokens
                    uint32_t kh[4], kl[4];
                    uint32_t ro = st + (uint32_t)((g * 16 + b_r) * ASTR) + colB;
                    ldsm_x4(ro, kh);
                    ldsm_x4(ro + AKSZ, kl);
                    mma16816(s[2*g],   qhf[j], kh[0], kh[1]);
                    mma16816(s[2*g],   qhf[j], kl[0], kl[1]);
                    mma16816(s[2*g],   qlf[j], kh[0], kh[1]);
                    mma16816(s[2*g+1], qhf[j], kh[2], kh[3]);
                    mma16816(s[2*g+1], qhf[j], kl[2], kl[3]);
                    mma16816(s[2*g+1], qlf[j], kh[2], kh[3]);
                }
            }

            // ---- causal mask (diagonal tiles only) ----
            if (kbase + 63 > wrow) {
                int rA = wrow + (lane >> 2), rB = rA + 8;
#pragma unroll
                for (int t = 0; t < 8; t++) {
                    int c0 = kbase + t * 8 + 2 * (lane & 3);
                    if (c0     > rA) s[t][0] = -1e30f;
                    if (c0 + 1 > rA) s[t][1] = -1e30f;
                    if (c0     > rB) s[t][2] = -1e30f;
                    if (c0 + 1 > rB) s[t][3] = -1e30f;
                }
            }

            // ---- online softmax ----
            float rmA = -1e30f, rmB = -1e30f;
#pragma unroll
            for (int t = 0; t < 8; t++) {
                rmA = fmaxf(rmA, fmaxf(s[t][0], s[t][1]));
                rmB = fmaxf(rmB, fmaxf(s[t][2], s[t][3]));
            }
            rmA = fmaxf(rmA, __shfl_xor_sync(0xffffffffu, rmA, 1));
            rmA = fmaxf(rmA, __shfl_xor_sync(0xffffffffu, rmA, 2));
            rmB = fmaxf(rmB, __shfl_xor_sync(0xffffffffu, rmB, 1));
            rmB = fmaxf(rmB, __shfl_xor_sync(0xffffffffu, rmB, 2));
            float mnA = fmaxf(mA, rmA), mnB = fmaxf(mB, rmB);
            float aA = __expf(mA - mnA), aB = __expf(mB - mnB);
            mA = mnA; mB = mnB;

            float rsA = 0.f, rsB = 0.f;
#pragma unroll
            for (int t = 0; t < 8; t++) {
                s[t][0] = __expf(s[t][0] - mnA);
                s[t][1] = __expf(s[t][1] - mnA);
                s[t][2] = __expf(s[t][2] - mnB);
                s[t][3] = __expf(s[t][3] - mnB);
                rsA += s[t][0] + s[t][1];
                rsB += s[t][2] + s[t][3];
            }
            rsA += __shfl_xor_sync(0xffffffffu, rsA, 1);
            rsA += __shfl_xor_sync(0xffffffffu, rsA, 2);
            rsB += __shfl_xor_sync(0xffffffffu, rsB, 1);
            rsB += __shfl_xor_sync(0xffffffffu, rsB, 2);
            lA = lA * aA + rsA;
            lB = lB * aB + rsB;
#pragma unroll
            for (int j = 0; j < 16; j++) {
                o[j][0] *= aA; o[j][1] *= aA;
                o[j][2] *= aB; o[j][3] *= aB;
            }

            // ---- O += P V (split x3) ----
#pragma unroll
            for (int t = 0; t < 4; t++) {        // k16 over 64 tokens
                uint32_t pah[4], pal[4];
                split2(s[2*t][0],   s[2*t][1],   pah[0], pal[0]);
                split2(s[2*t][2],   s[2*t][3],   pah[1], pal[1]);
                split2(s[2*t+1][0], s[2*t+1][1], pah[2], pal[2]);
                split2(s[2*t+1][2], s[2*t+1][3], pah[3], pal[3]);
                uint32_t vrow = st + 2 * AKSZ
                              + (uint32_t)((t * 16 + v_r) * ASTR);
#pragma unroll
                for (int g = 0; g < 8; g++) {    // n16 over D
                    uint32_t vh[4], vl[4];
                    uint32_t vo = vrow + (uint32_t)((g * 16 + v_c8) * 2);
                    ldsm_x4_trans(vo, vh);
                    ldsm_x4_trans(vo + AKSZ, vl);
                    mma16816(o[2*g],   pah, vh[0], vh[1]);
                    mma16816(o[2*g],   pah, vl[0], vl[1]);
                    mma16816(o[2*g],   pal, vh[0], vh[1]);
                    mma16816(o[2*g+1], pah, vh[2], vh[3]);
                    mma16816(o[2*g+1], pah, vl[2], vl[3]);
                    mma16816(o[2*g+1], pal, vh[2], vh[3]);
                }
            }
        }

        __syncthreads();
        if (kb + 2 < nkt)
            attn_load_kv(sb, kb & 1, Khg, Klg, Vhg, Vlg, (kb + 2) * 64, tid);
    }

    // ---- epilogue: normalize, split to hi/lo bf16 ----
    float ilA = 1.f / lA, ilB = 1.f / lB;
    int rowA = wrow + (lane >> 2);
#pragma unroll
    for (int j = 0; j < 16; j++) {
        int col = h * HD_ + j * 8 + 2 * (lane & 3);
        float v0 = o[j][0] * ilA, v1 = o[j][1] * ilA;
        float v2 = o[j][2] * ilB, v3 = o[j][3] * ilB;
        uint32_t hA, lAo, hB, lBo;
        split2(v0, v1, hA, lAo);
        split2(v2, v3, hB, lBo);
        *(uint32_t*)(g_atth + (size_t)rowA * HS_ + col) = hA;
        *(uint32_t*)(g_attl + (size_t)rowA * HS_ + col) = lAo;
        *(uint32_t*)(g_atth + (size_t)(rowA + 8) * HS_ + col) = hB;
        *(uint32_t*)(g_attl + (size_t)(rowA + 8) * HS_ + col) = lBo;
    }
}

// ======================= launcher ===========================================
extern "C" void kernel_launch(void* const* d_in, const int* in_sizes, int n_in,
                              void* d_out, int out_size) {
    const int*   positions = (const int*)d_in[0];
    const float* hidden    = (const float*)d_in[1];
    const float* ln_w      = (const float*)d_in[2];
    const float* qkv_w     = (const float*)d_in[3];
    const float* qkv_b     = (const float*)d_in[4];
    const float* qn_w      = (const float*)d_in[5];
    const float* kn_w      = (const float*)d_in[6];
    const float* o_w       = (const float*)d_in[7];
    float* out = (float*)d_out;

    void* p;
    cudaGetSymbolAddress(&p, g_xnh);  __nv_bfloat16* xnh = (__nv_bfloat16*)p;
    cudaGetSymbolAddress(&p, g_xnl);  __nv_bfloat16* xnl = (__nv_bfloat16*)p;
    cudaGetSymbolAddress(&p, g_wqh);  __nv_bfloat16* wqh = (__nv_bfloat16*)p;
    cudaGetSymbolAddress(&p, g_wql);  __nv_bfloat16* wql = (__nv_bfloat16*)p;
    cudaGetSymbolAddress(&p, g_woh);  __nv_bfloat16* woh = (__nv_bfloat16*)p;
    cudaGetSymbolAddress(&p, g_wol);  __nv_bfloat16* wol = (__nv_bfloat16*)p;
    cudaGetSymbolAddress(&p, g_atth); __nv_bfloat16* ath = (__nv_bfloat16*)p;
    cudaGetSymbolAddress(&p, g_attl); __nv_bfloat16* atl = (__nv_bfloat16*)p;
    cudaGetSymbolAddress(&p, g_qkv);  float* qkv = (float*)p;

    // weight splits (hi/lo)
    {
        int n1 = QKVN_ * HS_;
        cvt_split_kernel<<<n1 / 4 / 256, 256>>>(qkv_w, wqh, wql, n1);
        int n2 = HS_ * HS_;
        cvt_split_kernel<<<n2 / 4 / 256, 256>>>(o_w, woh, wol, n2);
    }

    // 1) RMSNorm(hidden) -> hi/lo
    rmsnorm_x_kernel<<<T_, 256>>>(hidden, ln_w);

    // 2) qkv = xn @ qkv_w^T + bias   (HMMA, warp 64x64, 6:1 MMA:LDSM)
    cudaFuncSetAttribute(gemm_bf16x3_kernel,
                         cudaFuncAttributeMaxDynamicSharedMemorySize, GEMM_SMEM);
    gemm_bf16x3_kernel<<<dim3(QKVN_ / BN, T_ / BM), 256, GEMM_SMEM>>>(
        xnh, xnl, wqh, wql, qkv_b, qkv, QKVN_, HS_);

    // 3) q/k RMSNorm + RoPE (scale folded into q), v split
    qk_rope_kernel<<<dim3(T_, NH_ + 2 * NKV_), 128>>>(positions, qn_w, kn_w);

    // 4) causal attention (tensor-core flash, split-bf16 x3)
    cudaFuncSetAttribute(attn_mma_kernel,
                         cudaFuncAttributeMaxDynamicSharedMemorySize, ATT_SMEM);
    attn_mma_kernel<<<dim3(T_ / 128, NH_), 256, ATT_SMEM>>>();

    // 5) out = att @ o_w^T
    gemm_bf16x3_kernel<<<dim3(HS_ / BN, T_ / BM), 256, GEMM_SMEM>>>(
        ath, atl, woh, wol, nullptr, out, HS_, HS_);
}

// round 7
// speedup vs baseline: 1.1922x; 1.0435x over previous
#include <cuda_runtime.h>
#include <cuda_bf16.h>
#include <cstdint>
#include <math.h>

#define T_   2048
#define HS_  4096
#define NH_  32
#define NKV_ 8
#define HD_  128
#define QKVN_ ((NH_ + 2*NKV_)*HD_)   // 6144

// ======================= helpers ===========================================
__device__ __forceinline__ uint32_t smem_to_u32(const void* smem_ptr) {
    uint32_t addr;
    asm("{ .reg .u64 tmp; cvta.to.shared.u64 tmp, %1; cvt.u32.u64 %0, tmp; }"
        : "=r"(addr) : "l"(smem_ptr));
    return addr;
}
__device__ __forceinline__ void ldsm_x4(uint32_t addr, uint32_t* r) {
    asm volatile("ldmatrix.sync.aligned.m8n8.x4.shared.b16 {%0,%1,%2,%3}, [%4];"
        : "=r"(r[0]), "=r"(r[1]), "=r"(r[2]), "=r"(r[3]) : "r"(addr));
}
__device__ __forceinline__ void ldsm_x4_trans(uint32_t addr, uint32_t* r) {
    asm volatile("ldmatrix.sync.aligned.m8n8.x4.trans.shared.b16 {%0,%1,%2,%3}, [%4];"
        : "=r"(r[0]), "=r"(r[1]), "=r"(r[2]), "=r"(r[3]) : "r"(addr));
}
__device__ __forceinline__ void mma16816(float* d, const uint32_t* a,
                                         const uint32_t b0, const uint32_t b1) {
    asm volatile("mma.sync.aligned.m16n8k16.row.col.f32.bf16.bf16.f32 "
        "{%0,%1,%2,%3}, {%4,%5,%6,%7}, {%8,%9}, {%0,%1,%2,%3};"
        : "+f"(d[0]), "+f"(d[1]), "+f"(d[2]), "+f"(d[3])
        : "r"(a[0]), "r"(a[1]), "r"(a[2]), "r"(a[3]), "r"(b0), "r"(b1));
}
__device__ __forceinline__ uint32_t pack_bf16(float a, float b) {
    __nv_bfloat162 t = __floats2bfloat162_rn(a, b);
    return *reinterpret_cast<uint32_t*>(&t);
}
__device__ __forceinline__ void split2(float a, float b,
                                       uint32_t& hi, uint32_t& lo) {
    __nv_bfloat16 ha = __float2bfloat16(a), hb = __float2bfloat16(b);
    hi = pack_bf16(__bfloat162float(ha), __bfloat162float(hb));
    lo = pack_bf16(a - __bfloat162float(ha), b - __bfloat162float(hb));
}

// ======================= scratch (device globals) ===========================
__device__ __align__(256) __nv_bfloat16 g_xnh[T_*HS_];
__device__ __align__(256) __nv_bfloat16 g_xnl[T_*HS_];
__device__ __align__(256) __nv_bfloat16 g_wqh[QKVN_*HS_];
__device__ __align__(256) __nv_bfloat16 g_wql[QKVN_*HS_];
__device__ __align__(256) __nv_bfloat16 g_woh[HS_*HS_];
__device__ __align__(256) __nv_bfloat16 g_wol[HS_*HS_];
__device__ __align__(256) __nv_bfloat16 g_atth[T_*HS_];
__device__ __align__(256) __nv_bfloat16 g_attl[T_*HS_];
__device__ float g_qkv[T_*QKVN_];
__device__ __align__(256) __nv_bfloat16 g_qh[NH_ *T_*HD_];
__device__ __align__(256) __nv_bfloat16 g_ql[NH_ *T_*HD_];
__device__ __align__(256) __nv_bfloat16 g_kh[NKV_*T_*HD_];
__device__ __align__(256) __nv_bfloat16 g_kl[NKV_*T_*HD_];
__device__ __align__(256) __nv_bfloat16 g_vh[NKV_*T_*HD_];
__device__ __align__(256) __nv_bfloat16 g_vl[NKV_*T_*HD_];

// ======================= kernel: fp32 -> (hi,lo) bf16 split =================
__global__ void cvt_split_kernel(const float* __restrict__ x,
                                 __nv_bfloat16* __restrict__ h,
                                 __nv_bfloat16* __restrict__ l, int n) {
    int i = (blockIdx.x * blockDim.x + threadIdx.x) * 4;
    if (i >= n) return;
    float4 v = *(const float4*)(x + i);
    __nv_bfloat16 h0 = __float2bfloat16(v.x);
    __nv_bfloat16 h1 = __float2bfloat16(v.y);
    __nv_bfloat16 h2 = __float2bfloat16(v.z);
    __nv_bfloat16 h3 = __float2bfloat16(v.w);
    __nv_bfloat162* hp = (__nv_bfloat162*)(h + i);
    __nv_bfloat162* lp = (__nv_bfloat162*)(l + i);
    hp[0] = __nv_bfloat162(h0, h1);
    hp[1] = __nv_bfloat162(h2, h3);
    lp[0] = __nv_bfloat162(__float2bfloat16(v.x - __bfloat162float(h0)),
                           __float2bfloat16(v.y - __bfloat162float(h1)));
    lp[1] = __nv_bfloat162(__float2bfloat16(v.z - __bfloat162float(h2)),
                           __float2bfloat16(v.w - __bfloat162float(h3)));
}

// ======================= kernel: RMSNorm(hidden) -> hi/lo bf16 ==============
__global__ void rmsnorm_x_kernel(const float* __restrict__ x,
                                 const float* __restrict__ w) {
    int row = blockIdx.x;
    const float* xr = x + (size_t)row * HS_;
    float ss = 0.f;
    for (int i = threadIdx.x; i < HS_; i += blockDim.x) {
        float v = xr[i];
        ss += v * v;
    }
    for (int off = 16; off; off >>= 1)
        ss += __shfl_xor_sync(0xffffffffu, ss, off);
    __shared__ float wr[8];
    int lane = threadIdx.x & 31, wid = threadIdx.x >> 5;
    if (lane == 0) wr[wid] = ss;
    __syncthreads();
    float tot = 0.f;
#pragma unroll
    for (int i = 0; i < 8; i++) tot += wr[i];
    float inv = rsqrtf(tot / (float)HS_ + 1e-6f);
    for (int i = threadIdx.x; i < HS_; i += blockDim.x) {
        float v = xr[i] * inv * w[i];
        __nv_bfloat16 h = __float2bfloat16(v);
        g_xnh[(size_t)row * HS_ + i] = h;
        g_xnl[(size_t)row * HS_ + i] = __float2bfloat16(v - __bfloat162float(h));
    }
}

// ======================= bf16 split GEMM: C = A*B^T (+bias) =================
// 128 threads, 4 warps (2x2), CTA 128x128, warp tile 64x64,
// 2-stage pipeline, 2 CTAs/SM. Per warp-k16-step: 16 LDSM : 96 MMA.
#define BM 128
#define BN 128
#define BK 32
#define ROWB 80                  // bytes per smem row: 40 bf16 (pad 32->40)
#define A_ARR (128 * ROWB)       // 10240 per array (A and B both 128 rows)
#define AL_OFF A_ARR
#define BH_OFF (2 * A_ARR)
#define BL_OFF (3 * A_ARR)
#define STG  (4 * A_ARR)         // 40960 bytes per stage
#define GEMM_SMEM (2 * STG)      // 81920 -> 2 CTAs/SM

__device__ __forceinline__ void gemm_load_stage(
    uint32_t sb, int stage,
    const __nv_bfloat16* __restrict__ Ah, const __nv_bfloat16* __restrict__ Al,
    const __nv_bfloat16* __restrict__ Bh, const __nv_bfloat16* __restrict__ Bl,
    int bm, int bn, int k0, int K, int tid)
{
    uint32_t base = sb + stage * STG;
    // 4 arrays x 128 rows x 4 chunks(16B) = 2048 chunks; 16 per thread
#pragma unroll
    for (int ii = 0; ii < 16; ii++) {
        int s = tid + ii * 128;
        int arr = s >> 9;                // 0=Ah 1=Al 2=Bh 3=Bl
        int r = (s >> 2) & 127, c = s & 3;
        const __nv_bfloat16* srcb =
            (arr == 0) ? Ah : (arr == 1) ? Al : (arr == 2) ? Bh : Bl;
        int grow = ((arr < 2) ? bm : bn) + r;
        const __nv_bfloat16* src = srcb + (size_t)grow * K + k0 + c * 8;
        uint32_t dst = base + arr * A_ARR + r * ROWB + c * 16;
        asm volatile("cp.async.cg.shared.global [%0], [%1], 16;"
                     :: "r"(dst), "l"(src));
    }
    asm volatile("cp.async.commit_group;" ::: "memory");
}

__global__ void __launch_bounds__(128, 2)
gemm_bf16x3_kernel(const __nv_bfloat16* __restrict__ Ah,
                   const __nv_bfloat16* __restrict__ Al,
                   const __nv_bfloat16* __restrict__ Bh,
                   const __nv_bfloat16* __restrict__ Bl,
                   const float* __restrict__ bias,
                   float* __restrict__ C, int N, int K)
{
    extern __shared__ char smem[];
    uint32_t sb = smem_to_u32(smem);
    int tid = threadIdx.x, lane = tid & 31, wid = tid >> 5;
    int wm = wid >> 1, wn = wid & 1;       // warp grid 2 x 2
    int bm = blockIdx.y * BM, bn = blockIdx.x * BN;
    int nk = K / BK;

    float acc[4][8][4];
#pragma unroll
    for (int i = 0; i < 4; i++)
#pragma unroll
        for (int j = 0; j < 8; j++)
#pragma unroll
            for (int c = 0; c < 4; c++) acc[i][j][c] = 0.f;

    gemm_load_stage(sb, 0, Ah, Al, Bh, Bl, bm, bn, 0,  K, tid);
    gemm_load_stage(sb, 1, Ah, Al, Bh, Bl, bm, bn, BK, K, tid);

    int a_r = (lane & 15);
    int a_c8 = (lane >> 4) << 3;
    int b_r = (lane & 7) + ((lane & 16) >> 1);
    int b_c8 = (lane & 8);

    for (int it = 0; it < nk; it++) {
        asm volatile("cp.async.wait_group 1;" ::: "memory");
        __syncthreads();

        uint32_t base = sb + (it & 1) * STG;

#pragma unroll
        for (int ks = 0; ks < BK; ks += 16) {
            int acolB = (ks + a_c8) * 2;
            int bcolB = (ks + b_c8) * 2;
            uint32_t bh[4][4], bl[4][4];
#pragma unroll
            for (int g = 0; g < 4; g++) {
                uint32_t ro = (uint32_t)((wn * 64 + g * 16 + b_r) * ROWB) + bcolB;
                ldsm_x4(base + BH_OFF + ro, bh[g]);
                ldsm_x4(base + BL_OFF + ro, bl[g]);
            }
#pragma unroll
            for (int mi = 0; mi < 4; mi++) {
                uint32_t ah[4], al[4];
                uint32_t ro = (uint32_t)((wm * 64 + mi * 16 + a_r) * ROWB) + acolB;
                ldsm_x4(base + ro, ah);
                ldsm_x4(base + AL_OFF + ro, al);
#pragma unroll
                for (int g = 0; g < 4; g++) {
                    mma16816(acc[mi][2*g],   ah, bh[g][0], bh[g][1]);
                    mma16816(acc[mi][2*g],   ah, bl[g][0], bl[g][1]);
                    mma16816(acc[mi][2*g],   al, bh[g][0], bh[g][1]);
                    mma16816(acc[mi][2*g+1], ah, bh[g][2], bh[g][3]);
                    mma16816(acc[mi][2*g+1], ah, bl[g][2], bl[g][3]);
                    mma16816(acc[mi][2*g+1], al, bh[g][2], bh[g][3]);
                }
            }
        }
        __syncthreads();
        if (it + 2 < nk)
            gemm_load_stage(sb, it & 1, Ah, Al, Bh, Bl, bm, bn,
                            (it + 2) * BK, K, tid);
    }

#pragma unroll
    for (int mi = 0; mi < 4; mi++) {
#pragma unroll
        for (int j = 0; j < 8; j++) {
            int r0 = bm + wm * 64 + mi * 16 + (lane >> 2);
            int c0 = bn + wn * 64 + j * 8 + 2 * (lane & 3);
            float b0 = 0.f, b1 = 0.f;
            if (bias) { b0 = bias[c0]; b1 = bias[c0 + 1]; }
            float2 v0 = make_float2(acc[mi][j][0] + b0, acc[mi][j][1] + b1);
            float2 v1 = make_float2(acc[mi][j][2] + b0, acc[mi][j][3] + b1);
            *(float2*)(C + (size_t)r0 * N + c0) = v0;
            *(float2*)(C + (size_t)(r0 + 8) * N + c0) = v1;
        }
    }
}

// ======================= kernel: per-head RMSNorm + RoPE -> hi/lo ===========
__global__ void qk_rope_kernel(const int* __restrict__ positions,
                               const float* __restrict__ qw,
                               const float* __restrict__ kw) {
    int t = blockIdx.x;
    int head = blockIdx.y;
    int i = threadIdx.x;   // 0..127
    float v = g_qkv[(size_t)t * QKVN_ + head * HD_ + i];

    if (head >= NH_ + NKV_) {   // v heads: split into hi/lo [KV,T,D]
        size_t idx = ((size_t)(head - NH_ - NKV_) * T_ + t) * HD_ + i;
        __nv_bfloat16 h = __float2bfloat16(v);
        g_vh[idx] = h;
        g_vl[idx] = __float2bfloat16(v - __bfloat162float(h));
        return;
    }

    float ss = v * v;
    for (int off = 16; off; off >>= 1)
        ss += __shfl_xor_sync(0xffffffffu, ss, off);
    __shared__ float wr[4];
    __shared__ float buf[HD_];
    int lane = i & 31, wid = i >> 5;
    if (lane == 0) wr[wid] = ss;
    __syncthreads();
    float tot = wr[0] + wr[1] + wr[2] + wr[3];
    float inv = rsqrtf(tot / (float)HD_ + 1e-6f);
    const float* w = (head < NH_) ? qw : kw;
    float nv = v * inv * w[i];
    buf[i] = nv;
    __syncthreads();

    int fi = i & 63;
    float invf = 1.0f / powf(10000.0f, (float)fi * (1.0f / 64.0f));
    float ang = (float)positions[t] * invf;
    float s, c;
    sincosf(ang, &s, &c);
    float other = buf[i ^ 64];
    float out = (i < 64) ? (nv * c - other * s) : (nv * c + other * s);

    if (head < NH_) {
        float sc = out * 0.08838834764831845f;   // fold in softmax scale
        size_t idx = ((size_t)head * T_ + t) * HD_ + i;
        __nv_bfloat16 h = __float2bfloat16(sc);
        g_qh[idx] = h;
        g_ql[idx] = __float2bfloat16(sc - __bfloat162float(h));
    } else {
        size_t idx = ((size_t)(head - NH_) * T_ + t) * HD_ + i;
        __nv_bfloat16 h = __float2bfloat16(out);
        g_kh[idx] = h;
        g_kl[idx] = __float2bfloat16(out - __bfloat162float(h));
    }
}

// ======================= tensor-core flash attention ========================
#define ASTR 272                    // smem row stride bytes (136 bf16)
#define AQSZ (128 * ASTR)           // 34816: one Q array (128 rows)
#define AKSZ (64 * ASTR)            // 17408: one K/V array (64 rows)
#define ASTAGE (4 * AKSZ)           // 69632: Kh,Kl,Vh,Vl
#define ATT_SMEM (2 * AQSZ + 2 * ASTAGE)   // 208896

__device__ __forceinline__ void attn_load_kv(
    uint32_t sb, int buf,
    const __nv_bfloat16* Kh, const __nv_bfloat16* Kl,
    const __nv_bfloat16* Vh, const __nv_bfloat16* Vl,
    int kt0, int tid)
{
    uint32_t base = sb + 2 * AQSZ + buf * ASTAGE;
#pragma unroll
    for (int ii = 0; ii < 16; ii++) {
        int s = tid + ii * 256;
        int arr = s >> 10;          // 0..3
        int r = (s >> 4) & 63;
        int c = s & 15;
        const __nv_bfloat16* src =
            (arr == 0) ? Kh : (arr == 1) ? Kl : (arr == 2) ? Vh : Vl;
        src += (size_t)(kt0 + r) * HD_ + c * 8;
        uint32_t dst = base + arr * AKSZ + r * ASTR + c * 16;
        asm volatile("cp.async.cg.shared.global [%0], [%1], 16;"
                     :: "r"(dst), "l"(src));
    }
    asm volatile("cp.async.commit_group;" ::: "memory");
}

__global__ void __launch_bounds__(256, 1) attn_mma_kernel() {
    extern __shared__ char smc[];
    uint32_t sb = smem_to_u32(smc);
    int qb = 15 - blockIdx.x;            // reversed: big workloads first
    int h  = blockIdx.y;
    int kvh = h >> 2;
    int tid = threadIdx.x, lane = tid & 31, wid = tid >> 5;

    const __nv_bfloat16* Qhg = g_qh + ((size_t)h * T_ + qb * 128) * HD_;
    const __nv_bfloat16* Qlg = g_ql + ((size_t)h * T_ + qb * 128) * HD_;
    const __nv_bfloat16* Khg = g_kh + (size_t)kvh * T_ * HD_;
    const __nv_bfloat16* Klg = g_kl + (size_t)kvh * T_ * HD_;
    const __nv_bfloat16* Vhg = g_vh + (size_t)kvh * T_ * HD_;
    const __nv_bfloat16* Vlg = g_vl + (size_t)kvh * T_ * HD_;

    // Q load (group 1)
#pragma unroll
    for (int ii = 0; ii < 16; ii++) {
        int s = tid + ii * 256;
        int arr = s >> 11;              // 0 = hi, 1 = lo
        int r = (s >> 4) & 127;
        int c = s & 15;
        const __nv_bfloat16* src = (arr ? Qlg : Qhg) + (size_t)r * HD_ + c * 8;
        uint32_t dst = sb + arr * AQSZ + r * ASTR + c * 16;
        asm volatile("cp.async.cg.shared.global [%0], [%1], 16;"
                     :: "r"(dst), "l"(src));
    }
    asm volatile("cp.async.commit_group;" ::: "memory");

    int nkt = 2 * qb + 2;
    attn_load_kv(sb, 0, Khg, Klg, Vhg, Vlg, 0,  tid);
    attn_load_kv(sb, 1, Khg, Klg, Vhg, Vlg, 64, tid);

    asm volatile("cp.async.wait_group 2;" ::: "memory");   // Q done
    __syncthreads();

    // extract Q fragments to registers
    int a_r = lane & 15, a_c8 = (lane >> 4) << 3;
    uint32_t qhf[8][4], qlf[8][4];
    {
        uint32_t qrow = (uint32_t)((wid * 16 + a_r) * ASTR);
#pragma unroll
        for (int j = 0; j < 8; j++) {
            uint32_t co = (uint32_t)((j * 16 + a_c8) * 2);
            ldsm_x4(sb + qrow + co, qhf[j]);
            ldsm_x4(sb + AQSZ + qrow + co, qlf[j]);
        }
    }

    float o[16][4];
#pragma unroll
    for (int j = 0; j < 16; j++)
#pragma unroll
        for (int c = 0; c < 4; c++) o[j][c] = 0.f;
    float mA = -1e30f, mB = -1e30f, lA = 0.f, lB = 0.f;

    int b_r = (lane & 7) + ((lane & 16) >> 1);   // K frag row map
    int b_c8 = (lane & 8);
    int v_r = (lane & 7) + 8 * ((lane >> 3) & 1);  // V trans frag row map
    int v_c8 = (lane >> 4) * 8;

    int wrow = qb * 128 + wid * 16;              // warp's first q row

    for (int kb = 0; kb < nkt; kb++) {
        asm volatile("cp.async.wait_group 1;" ::: "memory");
        __syncthreads();

        int kbase = kb * 64;
        bool active = (kbase <= wrow + 15);      // any unmasked element?
        uint32_t st = sb + 2 * AQSZ + (kb & 1) * ASTAGE;

        if (active) {
            // ---- S = Q K^T (split x3) ----
            float s[8][4];
#pragma unroll
            for (int t = 0; t < 8; t++)
#pragma unroll
                for (int c = 0; c < 4; c++) s[t][c] = 0.f;

#pragma unroll
            for (int j = 0; j < 8; j++) {        // k16 over D
                uint32_t colB = (uint32_t)((j * 16 + b_c8) * 2);
#pragma unroll
                for (int g = 0; g < 4; g++) {    // n16 over 64 tokens
                    uint32_t kh[4], kl[4];
                    uint32_t ro = st + (uint32_t)((g * 16 + b_r) * ASTR) + colB;
                    ldsm_x4(ro, kh);
                    ldsm_x4(ro + AKSZ, kl);
                    mma16816(s[2*g],   qhf[j], kh[0], kh[1]);
                    mma16816(s[2*g],   qhf[j], kl[0], kl[1]);
                    mma16816(s[2*g],   qlf[j], kh[0], kh[1]);
                    mma16816(s[2*g+1], qhf[j], kh[2], kh[3]);
                    mma16816(s[2*g+1], qhf[j], kl[2], kl[3]);
                    mma16816(s[2*g+1], qlf[j], kh[2], kh[3]);
                }
            }

            // ---- causal mask (diagonal tiles only) ----
            if (kbase + 63 > wrow) {
                int rA = wrow + (lane >> 2), rB = rA + 8;
#pragma unroll
                for (int t = 0; t < 8; t++) {
                    int c0 = kbase + t * 8 + 2 * (lane & 3);
                    if (c0     > rA) s[t][0] = -1e30f;
                    if (c0 + 1 > rA) s[t][1] = -1e30f;
                    if (c0     > rB) s[t][2] = -1e30f;
                    if (c0 + 1 > rB) s[t][3] = -1e30f;
                }
            }

            // ---- online softmax ----
            float rmA = -1e30f, rmB = -1e30f;
#pragma unroll
            for (int t = 0; t < 8; t++) {
                rmA = fmaxf(rmA, fmaxf(s[t][0], s[t][1]));
                rmB = fmaxf(rmB, fmaxf(s[t][2], s[t][3]));
            }
            rmA = fmaxf(rmA, __shfl_xor_sync(0xffffffffu, rmA, 1));
            rmA = fmaxf(rmA, __shfl_xor_sync(0xffffffffu, rmA, 2));
            rmB = fmaxf(rmB, __shfl_xor_sync(0xffffffffu, rmB, 1));
            rmB = fmaxf(rmB, __shfl_xor_sync(0xffffffffu, rmB, 2));
            float mnA = fmaxf(mA, rmA), mnB = fmaxf(mB, rmB);
            float aA = __expf(mA - mnA), aB = __expf(mB - mnB);
            mA = mnA; mB = mnB;

            float rsA = 0.f, rsB = 0.f;
#pragma unroll
            for (int t = 0; t < 8; t++) {
                s[t][0] = __expf(s[t][0] - mnA);
                s[t][1] = __expf(s[t][1] - mnA);
                s[t][2] = __expf(s[t][2] - mnB);
                s[t][3] = __expf(s[t][3] - mnB);
                rsA += s[t][0] + s[t][1];
                rsB += s[t][2] + s[t][3];
            }
            rsA += __shfl_xor_sync(0xffffffffu, rsA, 1);
            rsA += __shfl_xor_sync(0xffffffffu, rsA, 2);
            rsB += __shfl_xor_sync(0xffffffffu, rsB, 1);
            rsB += __shfl_xor_sync(0xffffffffu, rsB, 2);
            lA = lA * aA + rsA;
            lB = lB * aB + rsB;
#pragma unroll
            for (int j = 0; j < 16; j++) {
                o[j][0] *= aA; o[j][1] *= aA;
                o[j][2] *= aB; o[j][3] *= aB;
            }

            // ---- O += P V (split x3) ----
#pragma unroll
            for (int t = 0; t < 4; t++) {        // k16 over 64 tokens
                uint32_t pah[4], pal[4];
                split2(s[2*t][0],   s[2*t][1],   pah[0], pal[0]);
                split2(s[2*t][2],   s[2*t][3],   pah[1], pal[1]);
                split2(s[2*t+1][0], s[2*t+1][1], pah[2], pal[2]);
                split2(s[2*t+1][2], s[2*t+1][3], pah[3], pal[3]);
                uint32_t vrow = st + 2 * AKSZ
                              + (uint32_t)((t * 16 + v_r) * ASTR);
#pragma unroll
                for (int g = 0; g < 8; g++) {    // n16 over D
                    uint32_t vh[4], vl[4];
                    uint32_t vo = vrow + (uint32_t)((g * 16 + v_c8) * 2);
                    ldsm_x4_trans(vo, vh);
                    ldsm_x4_trans(vo + AKSZ, vl);
                    mma16816(o[2*g],   pah, vh[0], vh[1]);
                    mma16816(o[2*g],   pah, vl[0], vl[1]);
                    mma16816(o[2*g],   pal, vh[0], vh[1]);
                    mma16816(o[2*g+1], pah, vh[2], vh[3]);
                    mma16816(o[2*g+1], pah, vl[2], vl[3]);
                    mma16816(o[2*g+1], pal, vh[2], vh[3]);
                }
            }
        }

        __syncthreads();
        if (kb + 2 < nkt)
            attn_load_kv(sb, kb & 1, Khg, Klg, Vhg, Vlg, (kb + 2) * 64, tid);
    }

    // ---- epilogue: normalize, split to hi/lo bf16 ----
    float ilA = 1.f / lA, ilB = 1.f / lB;
    int rowA = wrow + (lane >> 2);
#pragma unroll
    for (int j = 0; j < 16; j++) {
        int col = h * HD_ + j * 8 + 2 * (lane & 3);
        float v0 = o[j][0] * ilA, v1 = o[j][1] * ilA;
        float v2 = o[j][2] * ilB, v3 = o[j][3] * ilB;
        uint32_t hA, lAo, hB, lBo;
        split2(v0, v1, hA, lAo);
        split2(v2, v3, hB, lBo);
        *(uint32_t*)(g_atth + (size_t)rowA * HS_ + col) = hA;
        *(uint32_t*)(g_attl + (size_t)rowA * HS_ + col) = lAo;
        *(uint32_t*)(g_atth + (size_t)(rowA + 8) * HS_ + col) = hB;
        *(uint32_t*)(g_attl + (size_t)(rowA + 8) * HS_ + col) = lBo;
    }
}

// ======================= launcher ===========================================
extern "C" void kernel_launch(void* const* d_in, const int* in_sizes, int n_in,
                              void* d_out, int out_size) {
    const int*   positions = (const int*)d_in[0];
    const float* hidden    = (const float*)d_in[1];
    const float* ln_w      = (const float*)d_in[2];
    const float* qkv_w     = (const float*)d_in[3];
    const float* qkv_b     = (const float*)d_in[4];
    const float* qn_w      = (const float*)d_in[5];
    const float* kn_w      = (const float*)d_in[6];
    const float* o_w       = (const float*)d_in[7];
    float* out = (float*)d_out;

    void* p;
    cudaGetSymbolAddress(&p, g_xnh);  __nv_bfloat16* xnh = (__nv_bfloat16*)p;
    cudaGetSymbolAddress(&p, g_xnl);  __nv_bfloat16* xnl = (__nv_bfloat16*)p;
    cudaGetSymbolAddress(&p, g_wqh);  __nv_bfloat16* wqh = (__nv_bfloat16*)p;
    cudaGetSymbolAddress(&p, g_wql);  __nv_bfloat16* wql = (__nv_bfloat16*)p;
    cudaGetSymbolAddress(&p, g_woh);  __nv_bfloat16* woh = (__nv_bfloat16*)p;
    cudaGetSymbolAddress(&p, g_wol);  __nv_bfloat16* wol = (__nv_bfloat16*)p;
    cudaGetSymbolAddress(&p, g_atth); __nv_bfloat16* ath = (__nv_bfloat16*)p;
    cudaGetSymbolAddress(&p, g_attl); __nv_bfloat16* atl = (__nv_bfloat16*)p;
    cudaGetSymbolAddress(&p, g_qkv);  float* qkv = (float*)p;

    // weight splits (hi/lo)
    {
        int n1 = QKVN_ * HS_;
        cvt_split_kernel<<<n1 / 4 / 256, 256>>>(qkv_w, wqh, wql, n1);
        int n2 = HS_ * HS_;
        cvt_split_kernel<<<n2 / 4 / 256, 256>>>(o_w, woh, wol, n2);
    }

    // 1) RMSNorm(hidden) -> hi/lo
    rmsnorm_x_kernel<<<T_, 256>>>(hidden, ln_w);

    // 2) qkv = xn @ qkv_w^T + bias   (HMMA, warp 64x64, 2 CTAs/SM)
    cudaFuncSetAttribute(gemm_bf16x3_kernel,
                         cudaFuncAttributeMaxDynamicSharedMemorySize, GEMM_SMEM);
    gemm_bf16x3_kernel<<<dim3(QKVN_ / BN, T_ / BM), 128, GEMM_SMEM>>>(
        xnh, xnl, wqh, wql, qkv_b, qkv, QKVN_, HS_);

    // 3) q/k RMSNorm + RoPE (scale folded into q), v split
    qk_rope_kernel<<<dim3(T_, NH_ + 2 * NKV_), 128>>>(positions, qn_w, kn_w);

    // 4) causal attention (tensor-core flash, split-bf16 x3)
    cudaFuncSetAttribute(attn_mma_kernel,
                         cudaFuncAttributeMaxDynamicSharedMemorySize, ATT_SMEM);
    attn_mma_kernel<<<dim3(T_ / 128, NH_), 256, ATT_SMEM>>>();

    // 5) out = att @ o_w^T
    gemm_bf16x3_kernel<<<dim3(HS_ / BN, T_ / BM), 128, GEMM_SMEM>>>(
        ath, atl, woh, wol, nullptr, out, HS_, HS_);
}

// round 8
// speedup vs baseline: 1.6565x; 1.3895x over previous
#include <cuda_runtime.h>
#include <cuda_fp16.h>
#include <cstdint>
#include <math.h>

#define T_   2048
#define HS_  4096
#define NH_  32
#define NKV_ 8
#define HD_  128
#define QKVN_ ((NH_ + 2*NKV_)*HD_)   // 6144

// ======================= helpers ===========================================
__device__ __forceinline__ uint32_t smem_to_u32(const void* smem_ptr) {
    uint32_t addr;
    asm("{ .reg .u64 tmp; cvta.to.shared.u64 tmp, %1; cvt.u32.u64 %0, tmp; }"
        : "=r"(addr) : "l"(smem_ptr));
    return addr;
}
__device__ __forceinline__ void ldsm_x4(uint32_t addr, uint32_t* r) {
    asm volatile("ldmatrix.sync.aligned.m8n8.x4.shared.b16 {%0,%1,%2,%3}, [%4];"
        : "=r"(r[0]), "=r"(r[1]), "=r"(r[2]), "=r"(r[3]) : "r"(addr));
}
__device__ __forceinline__ void ldsm_x4_trans(uint32_t addr, uint32_t* r) {
    asm volatile("ldmatrix.sync.aligned.m8n8.x4.trans.shared.b16 {%0,%1,%2,%3}, [%4];"
        : "=r"(r[0]), "=r"(r[1]), "=r"(r[2]), "=r"(r[3]) : "r"(addr));
}
__device__ __forceinline__ void mma16816(float* d, const uint32_t* a,
                                         const uint32_t b0, const uint32_t b1) {
    asm volatile("mma.sync.aligned.m16n8k16.row.col.f32.f16.f16.f32 "
        "{%0,%1,%2,%3}, {%4,%5,%6,%7}, {%8,%9}, {%0,%1,%2,%3};"
        : "+f"(d[0]), "+f"(d[1]), "+f"(d[2]), "+f"(d[3])
        : "r"(a[0]), "r"(a[1]), "r"(a[2]), "r"(a[3]), "r"(b0), "r"(b1));
}
__device__ __forceinline__ uint32_t packh(float a, float b) {
    __half2 t = __floats2half2_rn(a, b);
    return *reinterpret_cast<uint32_t*>(&t);
}
__device__ __forceinline__ void split2h(float a, float b,
                                        uint32_t& hi, uint32_t& lo) {
    __half ha = __float2half_rn(a), hb = __float2half_rn(b);
    hi = packh(__half2float(ha), __half2float(hb));
    lo = packh(a - __half2float(ha), b - __half2float(hb));
}

// ======================= scratch (device globals) ===========================
__device__ __align__(256) __half g_xnh[T_*HS_];
__device__ __align__(256) __half g_xnl[T_*HS_];
__device__ __align__(256) __half g_wq [QKVN_*HS_];
__device__ __align__(256) __half g_wo [HS_*HS_];
__device__ __align__(256) __half g_atth[T_*HS_];
__device__ __align__(256) __half g_attl[T_*HS_];
__device__ float g_qkv[T_*QKVN_];
__device__ __align__(256) __half g_qh[NH_ *T_*HD_];
__device__ __align__(256) __half g_ql[NH_ *T_*HD_];
__device__ __align__(256) __half g_k [NKV_*T_*HD_];
__device__ __align__(256) __half g_v [NKV_*T_*HD_];

// ======================= kernel: fp32 -> fp16 ================================
__global__ void cvt_half_kernel(const float* __restrict__ x,
                                __half* __restrict__ h, int n) {
    int i = (blockIdx.x * blockDim.x + threadIdx.x) * 4;
    if (i >= n) return;
    float4 v = *(const float4*)(x + i);
    __half2* hp = (__half2*)(h + i);
    hp[0] = __floats2half2_rn(v.x, v.y);
    hp[1] = __floats2half2_rn(v.z, v.w);
}

// ======================= kernel: RMSNorm(hidden) -> hi/lo fp16 ==============
__global__ void rmsnorm_x_kernel(const float* __restrict__ x,
                                 const float* __restrict__ w) {
    int row = blockIdx.x;
    const float* xr = x + (size_t)row * HS_;
    float ss = 0.f;
    for (int i = threadIdx.x; i < HS_; i += blockDim.x) {
        float v = xr[i];
        ss += v * v;
    }
    for (int off = 16; off; off >>= 1)
        ss += __shfl_xor_sync(0xffffffffu, ss, off);
    __shared__ float wr[8];
    int lane = threadIdx.x & 31, wid = threadIdx.x >> 5;
    if (lane == 0) wr[wid] = ss;
    __syncthreads();
    float tot = 0.f;
#pragma unroll
    for (int i = 0; i < 8; i++) tot += wr[i];
    float inv = rsqrtf(tot / (float)HS_ + 1e-6f);
    for (int i = threadIdx.x; i < HS_; i += blockDim.x) {
        float v = xr[i] * inv * w[i];
        __half h = __float2half_rn(v);
        g_xnh[(size_t)row * HS_ + i] = h;
        g_xnl[(size_t)row * HS_ + i] = __float2half_rn(v - __half2float(h));
    }
}

// ======================= fp16 2-pass GEMM: C = A*B^T (+bias) ================
// A split hi/lo fp16, B single fp16. 128 threads, 4 warps (2x2),
// CTA 128x128, warp tile 64x64, 3-stage pipeline, 2 CTAs/SM.
#define BM 128
#define BN 128
#define BK 32
#define ROWB 80                  // bytes per smem row: 40 fp16 (pad 32->40)
#define A_ARR (128 * ROWB)       // 10240 per array
#define AL_OFF A_ARR
#define B_OFF  (2 * A_ARR)
#define STG  (3 * A_ARR)         // 30720 bytes per stage
#define GEMM_SMEM (3 * STG)      // 92160 -> 2 CTAs/SM

__device__ __forceinline__ void gemm_load_stage(
    uint32_t sb, int stage,
    const __half* __restrict__ Ah, const __half* __restrict__ Al,
    const __half* __restrict__ B,
    int bm, int bn, int k0, int K, int tid)
{
    uint32_t base = sb + stage * STG;
    // 3 arrays x 128 rows x 4 chunks(16B) = 1536 chunks; 12 per thread
#pragma unroll
    for (int ii = 0; ii < 12; ii++) {
        int s = tid + ii * 128;
        int arr = s >> 9;                // 0=Ah 1=Al 2=B
        int r = (s >> 2) & 127, c = s & 3;
        const __half* srcb = (arr == 0) ? Ah : (arr == 1) ? Al : B;
        int grow = ((arr < 2) ? bm : bn) + r;
        const __half* src = srcb + (size_t)grow * K + k0 + c * 8;
        uint32_t dst = base + arr * A_ARR + r * ROWB + c * 16;
        asm volatile("cp.async.cg.shared.global [%0], [%1], 16;"
                     :: "r"(dst), "l"(src));
    }
    asm volatile("cp.async.commit_group;" ::: "memory");
}

__global__ void __launch_bounds__(128, 2)
gemm_fp16x2_kernel(const __half* __restrict__ Ah,
                   const __half* __restrict__ Al,
                   const __half* __restrict__ B,
                   const float* __restrict__ bias,
                   float* __restrict__ C, int N, int K)
{
    extern __shared__ char smem[];
    uint32_t sb = smem_to_u32(smem);
    int tid = threadIdx.x, lane = tid & 31, wid = tid >> 5;
    int wm = wid >> 1, wn = wid & 1;       // warp grid 2 x 2
    int bm = blockIdx.y * BM, bn = blockIdx.x * BN;
    int nk = K / BK;

    float acc[4][8][4];
#pragma unroll
    for (int i = 0; i < 4; i++)
#pragma unroll
        for (int j = 0; j < 8; j++)
#pragma unroll
            for (int c = 0; c < 4; c++) acc[i][j][c] = 0.f;

    gemm_load_stage(sb, 0, Ah, Al, B, bm, bn, 0,      K, tid);
    gemm_load_stage(sb, 1, Ah, Al, B, bm, bn, BK,     K, tid);
    gemm_load_stage(sb, 2, Ah, Al, B, bm, bn, 2 * BK, K, tid);

    int a_r = (lane & 15);
    int a_c8 = (lane >> 4) << 3;
    int b_r = (lane & 7) + ((lane & 16) >> 1);
    int b_c8 = (lane & 8);

    for (int it = 0; it < nk; it++) {
        asm volatile("cp.async.wait_group 2;" ::: "memory");
        __syncthreads();

        uint32_t base = sb + (it % 3) * STG;

#pragma unroll
        for (int ks = 0; ks < BK; ks += 16) {
            int acolB = (ks + a_c8) * 2;
            int bcolB = (ks + b_c8) * 2;
            uint32_t bh[4][4];
#pragma unroll
            for (int g = 0; g < 4; g++) {
                uint32_t ro = (uint32_t)((wn * 64 + g * 16 + b_r) * ROWB) + bcolB;
                ldsm_x4(base + B_OFF + ro, bh[g]);
            }
#pragma unroll
            for (int mi = 0; mi < 4; mi++) {
                uint32_t ah[4], al[4];
                uint32_t ro = (uint32_t)((wm * 64 + mi * 16 + a_r) * ROWB) + acolB;
                ldsm_x4(base + ro, ah);
                ldsm_x4(base + AL_OFF + ro, al);
#pragma unroll
                for (int g = 0; g < 4; g++) {
                    mma16816(acc[mi][2*g],   ah, bh[g][0], bh[g][1]);
                    mma16816(acc[mi][2*g],   al, bh[g][0], bh[g][1]);
                    mma16816(acc[mi][2*g+1], ah, bh[g][2], bh[g][3]);
                    mma16816(acc[mi][2*g+1], al, bh[g][2], bh[g][3]);
                }
            }
        }
        __syncthreads();
        if (it + 3 < nk)
            gemm_load_stage(sb, it % 3, Ah, Al, B, bm, bn,
                            (it + 3) * BK, K, tid);
    }

#pragma unroll
    for (int mi = 0; mi < 4; mi++) {
#pragma unroll
        for (int j = 0; j < 8; j++) {
            int r0 = bm + wm * 64 + mi * 16 + (lane >> 2);
            int c0 = bn + wn * 64 + j * 8 + 2 * (lane & 3);
            float b0 = 0.f, b1 = 0.f;
            if (bias) { b0 = bias[c0]; b1 = bias[c0 + 1]; }
            float2 v0 = make_float2(acc[mi][j][0] + b0, acc[mi][j][1] + b1);
            float2 v1 = make_float2(acc[mi][j][2] + b0, acc[mi][j][3] + b1);
            *(float2*)(C + (size_t)r0 * N + c0) = v0;
            *(float2*)(C + (size_t)(r0 + 8) * N + c0) = v1;
        }
    }
}

// ======================= kernel: per-head RMSNorm + RoPE ====================
__global__ void qk_rope_kernel(const int* __restrict__ positions,
                               const float* __restrict__ qw,
                               const float* __restrict__ kw) {
    int t = blockIdx.x;
    int head = blockIdx.y;
    int i = threadIdx.x;   // 0..127
    float v = g_qkv[(size_t)t * QKVN_ + head * HD_ + i];

    if (head >= NH_ + NKV_) {   // v heads: single fp16 [KV,T,D]
        size_t idx = ((size_t)(head - NH_ - NKV_) * T_ + t) * HD_ + i;
        g_v[idx] = __float2half_rn(v);
        return;
    }

    float ss = v * v;
    for (int off = 16; off; off >>= 1)
        ss += __shfl_xor_sync(0xffffffffu, ss, off);
    __shared__ float wr[4];
    __shared__ float buf[HD_];
    int lane = i & 31, wid = i >> 5;
    if (lane == 0) wr[wid] = ss;
    __syncthreads();
    float tot = wr[0] + wr[1] + wr[2] + wr[3];
    float inv = rsqrtf(tot / (float)HD_ + 1e-6f);
    const float* w = (head < NH_) ? qw : kw;
    float nv = v * inv * w[i];
    buf[i] = nv;
    __syncthreads();

    int fi = i & 63;
    float invf = 1.0f / powf(10000.0f, (float)fi * (1.0f / 64.0f));
    float ang = (float)positions[t] * invf;
    float s, c;
    sincosf(ang, &s, &c);
    float other = buf[i ^ 64];
    float out = (i < 64) ? (nv * c - other * s) : (nv * c + other * s);

    if (head < NH_) {
        float sc = out * 0.08838834764831845f;   // fold in softmax scale
        size_t idx = ((size_t)head * T_ + t) * HD_ + i;
        __half h = __float2half_rn(sc);
        g_qh[idx] = h;
        g_ql[idx] = __float2half_rn(sc - __half2float(h));
    } else {
        size_t idx = ((size_t)(head - NH_) * T_ + t) * HD_ + i;
        g_k[idx] = __float2half_rn(out);
    }
}

// ======================= tensor-core flash attention (fp16 2-pass) ==========
#define ASTR 272                    // smem row stride bytes (136 fp16)
#define AQSZ (128 * ASTR)           // 34816: one Q array (128 rows)
#define AKSZ (64 * ASTR)            // 17408: one K or V array (64 rows)
#define ASTAGE (2 * AKSZ)           // 34816: K,V
#define ATT_SMEM (2 * AQSZ + 2 * ASTAGE)   // 139264

__device__ __forceinline__ void attn_load_kv(
    uint32_t sb, int buf,
    const __half* K, const __half* V,
    int kt0, int tid)
{
    uint32_t base = sb + 2 * AQSZ + buf * ASTAGE;
    // 2 arrays x 64 rows x 16 chunks = 2048 chunks; 8 per thread
#pragma unroll
    for (int ii = 0; ii < 8; ii++) {
        int s = tid + ii * 256;
        int arr = s >> 10;          // 0=K 1=V
        int r = (s >> 4) & 63;
        int c = s & 15;
        const __half* src = (arr ? V : K) + (size_t)(kt0 + r) * HD_ + c * 8;
        uint32_t dst = base + arr * AKSZ + r * ASTR + c * 16;
        asm volatile("cp.async.cg.shared.global [%0], [%1], 16;"
                     :: "r"(dst), "l"(src));
    }
    asm volatile("cp.async.commit_group;" ::: "memory");
}

__global__ void __launch_bounds__(256, 1) attn_mma_kernel() {
    extern __shared__ char smc[];
    uint32_t sb = smem_to_u32(smc);
    int qb = 15 - blockIdx.x;            // reversed: big workloads first
    int h  = blockIdx.y;
    int kvh = h >> 2;
    int tid = threadIdx.x, lane = tid & 31, wid = tid >> 5;

    const __half* Qhg = g_qh + ((size_t)h * T_ + qb * 128) * HD_;
    const __half* Qlg = g_ql + ((size_t)h * T_ + qb * 128) * HD_;
    const __half* Kg  = g_k  + (size_t)kvh * T_ * HD_;
    const __half* Vg  = g_v  + (size_t)kvh * T_ * HD_;

    // Q load (2 arrays x 128 rows x 16 chunks = 4096 chunks; 16/thread)
#pragma unroll
    for (int ii = 0; ii < 16; ii++) {
        int s = tid + ii * 256;
        int arr = s >> 11;              // 0 = hi, 1 = lo
        int r = (s >> 4) & 127;
        int c = s & 15;
        const __half* src = (arr ? Qlg : Qhg) + (size_t)r * HD_ + c * 8;
        uint32_t dst = sb + arr * AQSZ + r * ASTR + c * 16;
        asm volatile("cp.async.cg.shared.global [%0], [%1], 16;"
                     :: "r"(dst), "l"(src));
    }
    asm volatile("cp.async.commit_group;" ::: "memory");

    int nkt = 2 * qb + 2;
    attn_load_kv(sb, 0, Kg, Vg, 0,  tid);
    attn_load_kv(sb, 1, Kg, Vg, 64, tid);

    asm volatile("cp.async.wait_group 2;" ::: "memory");   // Q done
    __syncthreads();

    // extract Q fragments to registers
    int a_r = lane & 15, a_c8 = (lane >> 4) << 3;
    uint32_t qhf[8][4], qlf[8][4];
    {
        uint32_t qrow = (uint32_t)((wid * 16 + a_r) * ASTR);
#pragma unroll
        for (int j = 0; j < 8; j++) {
            uint32_t co = (uint32_t)((j * 16 + a_c8) * 2);
            ldsm_x4(sb + qrow + co, qhf[j]);
            ldsm_x4(sb + AQSZ + qrow + co, qlf[j]);
        }
    }

    float o[16][4];
#pragma unroll
    for (int j = 0; j < 16; j++)
#pragma unroll
        for (int c = 0; c < 4; c++) o[j][c] = 0.f;
    float mA = -1e30f, mB = -1e30f, lA = 0.f, lB = 0.f;

    int b_r = (lane & 7) + ((lane & 16) >> 1);   // K frag row map
    int b_c8 = (lane & 8);
    int v_r = (lane & 7) + 8 * ((lane >> 3) & 1);  // V trans frag row map
    int v_c8 = (lane >> 4) * 8;

    int wrow = qb * 128 + wid * 16;              // warp's first q row

    for (int kb = 0; kb < nkt; kb++) {
        asm volatile("cp.async.wait_group 1;" ::: "memory");
        __syncthreads();

        int kbase = kb * 64;
        bool active = (kbase <= wrow + 15);      // any unmasked element?
        uint32_t st = sb + 2 * AQSZ + (kb & 1) * ASTAGE;

        if (active) {
            // ---- S = Q K^T (Q split x2, K single) ----
            float s[8][4];
#pragma unroll
            for (int t = 0; t < 8; t++)
#pragma unroll
                for (int c = 0; c < 4; c++) s[t][c] = 0.f;

#pragma unroll
            for (int j = 0; j < 8; j++) {        // k16 over D
                uint32_t colB = (uint32_t)((j * 16 + b_c8) * 2);
#pragma unroll
                for (int g = 0; g < 4; g++) {    // n16 over 64 tokens
                    uint32_t kh[4];
                    uint32_t ro = st + (uint32_t)((g * 16 + b_r) * ASTR) + colB;
                    ldsm_x4(ro, kh);
                    mma16816(s[2*g],   qhf[j], kh[0], kh[1]);
                    mma16816(s[2*g],   qlf[j], kh[0], kh[1]);
                    mma16816(s[2*g+1], qhf[j], kh[2], kh[3]);
                    mma16816(s[2*g+1], qlf[j], kh[2], kh[3]);
                }
            }

            // ---- causal mask (diagonal tiles only) ----
            if (kbase + 63 > wrow) {
                int rA = wrow + (lane >> 2), rB = rA + 8;
#pragma unroll
                for (int t = 0; t < 8; t++) {
                    int c0 = kbase + t * 8 + 2 * (lane & 3);
                    if (c0     > rA) s[t][0] = -1e30f;
                    if (c0 + 1 > rA) s[t][1] = -1e30f;
                    if (c0     > rB) s[t][2] = -1e30f;
                    if (c0 + 1 > rB) s[t][3] = -1e30f;
                }
            }

            // ---- online softmax ----
            float rmA = -1e30f, rmB = -1e30f;
#pragma unroll
            for (int t = 0; t < 8; t++) {
                rmA = fmaxf(rmA, fmaxf(s[t][0], s[t][1]));
                rmB = fmaxf(rmB, fmaxf(s[t][2], s[t][3]));
            }
            rmA = fmaxf(rmA, __shfl_xor_sync(0xffffffffu, rmA, 1));
            rmA = fmaxf(rmA, __shfl_xor_sync(0xffffffffu, rmA, 2));
            rmB = fmaxf(rmB, __shfl_xor_sync(0xffffffffu, rmB, 1));
            rmB = fmaxf(rmB, __shfl_xor_sync(0xffffffffu, rmB, 2));
            float mnA = fmaxf(mA, rmA), mnB = fmaxf(mB, rmB);
            float aA = __expf(mA - mnA), aB = __expf(mB - mnB);
            mA = mnA; mB = mnB;

            float rsA = 0.f, rsB = 0.f;
#pragma unroll
            for (int t = 0; t < 8; t++) {
                s[t][0] = __expf(s[t][0] - mnA);
                s[t][1] = __expf(s[t][1] - mnA);
                s[t][2] = __expf(s[t][2] - mnB);
                s[t][3] = __expf(s[t][3] - mnB);
                rsA += s[t][0] + s[t][1];
                rsB += s[t][2] + s[t][3];
            }
            rsA += __shfl_xor_sync(0xffffffffu, rsA, 1);
            rsA += __shfl_xor_sync(0xffffffffu, rsA, 2);
            rsB += __shfl_xor_sync(0xffffffffu, rsB, 1);
            rsB += __shfl_xor_sync(0xffffffffu, rsB, 2);
            lA = lA * aA + rsA;
            lB = lB * aB + rsB;
#pragma unroll
            for (int j = 0; j < 16; j++) {
                o[j][0] *= aA; o[j][1] *= aA;
                o[j][2] *= aB; o[j][3] *= aB;
            }

            // ---- O += P V (P split x2, V single) ----
#pragma unroll
            for (int t = 0; t < 4; t++) {        // k16 over 64 tokens
                uint32_t pah[4], pal[4];
                split2h(s[2*t][0],   s[2*t][1],   pah[0], pal[0]);
                split2h(s[2*t][2],   s[2*t][3],   pah[1], pal[1]);
                split2h(s[2*t+1][0], s[2*t+1][1], pah[2], pal[2]);
                split2h(s[2*t+1][2], s[2*t+1][3], pah[3], pal[3]);
                uint32_t vrow = st + AKSZ
                              + (uint32_t)((t * 16 + v_r) * ASTR);
#pragma unroll
                for (int g = 0; g < 8; g++) {    // n16 over D
                    uint32_t vh[4];
                    uint32_t vo = vrow + (uint32_t)((g * 16 + v_c8) * 2);
                    ldsm_x4_trans(vo, vh);
                    mma16816(o[2*g],   pah, vh[0], vh[1]);
                    mma16816(o[2*g],   pal, vh[0], vh[1]);
                    mma16816(o[2*g+1], pah, vh[2], vh[3]);
                    mma16816(o[2*g+1], pal, vh[2], vh[3]);
                }
            }
        }

        __syncthreads();
        if (kb + 2 < nkt)
            attn_load_kv(sb, kb & 1, Kg, Vg, (kb + 2) * 64, tid);
    }

    // ---- epilogue: normalize, split to hi/lo fp16 ----
    float ilA = 1.f / lA, ilB = 1.f / lB;
    int rowA = wrow + (lane >> 2);
#pragma unroll
    for (int j = 0; j < 16; j++) {
        int col = h * HD_ + j * 8 + 2 * (lane & 3);
        float v0 = o[j][0] * ilA, v1 = o[j][1] * ilA;
        float v2 = o[j][2] * ilB, v3 = o[j][3] * ilB;
        uint32_t hA, lAo, hB, lBo;
        split2h(v0, v1, hA, lAo);
        split2h(v2, v3, hB, lBo);
        *(uint32_t*)(g_atth + (size_t)rowA * HS_ + col) = hA;
        *(uint32_t*)(g_attl + (size_t)rowA * HS_ + col) = lAo;
        *(uint32_t*)(g_atth + (size_t)(rowA + 8) * HS_ + col) = hB;
        *(uint32_t*)(g_attl + (size_t)(rowA + 8) * HS_ + col) = lBo;
    }
}

// ======================= launcher ===========================================
extern "C" void kernel_launch(void* const* d_in, const int* in_sizes, int n_in,
                              void* d_out, int out_size) {
    const int*   positions = (const int*)d_in[0];
    const float* hidden    = (const float*)d_in[1];
    const float* ln_w      = (const float*)d_in[2];
    const float* qkv_w     = (const float*)d_in[3];
    const float* qkv_b     = (const float*)d_in[4];
    const float* qn_w      = (const float*)d_in[5];
    const float* kn_w      = (const float*)d_in[6];
    const float* o_w       = (const float*)d_in[7];
    float* out = (float*)d_out;

    void* p;
    cudaGetSymbolAddress(&p, g_xnh);  __half* xnh = (__half*)p;
    cudaGetSymbolAddress(&p, g_xnl);  __half* xnl = (__half*)p;
    cudaGetSymbolAddress(&p, g_wq);   __half* wq  = (__half*)p;
    cudaGetSymbolAddress(&p, g_wo);   __half* wo  = (__half*)p;
    cudaGetSymbolAddress(&p, g_atth); __half* ath = (__half*)p;
    cudaGetSymbolAddress(&p, g_attl); __half* atl = (__half*)p;
    cudaGetSymbolAddress(&p, g_qkv);  float* qkv = (float*)p;

    // weight conversion (single fp16)
    {
        int n1 = QKVN_ * HS_;
        cvt_half_kernel<<<n1 / 4 / 256, 256>>>(qkv_w, wq, n1);
        int n2 = HS_ * HS_;
        cvt_half_kernel<<<n2 / 4 / 256, 256>>>(o_w, wo, n2);
    }

    // 1) RMSNorm(hidden) -> hi/lo fp16
    rmsnorm_x_kernel<<<T_, 256>>>(hidden, ln_w);

    // 2) qkv = xn @ qkv_w^T + bias   (fp16 2-pass HMMA)
    cudaFuncSetAttribute(gemm_fp16x2_kernel,
                         cudaFuncAttributeMaxDynamicSharedMemorySize, GEMM_SMEM);
    gemm_fp16x2_kernel<<<dim3(QKVN_ / BN, T_ / BM), 128, GEMM_SMEM>>>(
        xnh, xnl, wq, qkv_b, qkv, QKVN_, HS_);

    // 3) q/k RMSNorm + RoPE (scale folded into q; q split, k/v single fp16)
    qk_rope_kernel<<<dim3(T_, NH_ + 2 * NKV_), 128>>>(positions, qn_w, kn_w);

    // 4) causal attention (fp16 2-pass flash)
    cudaFuncSetAttribute(attn_mma_kernel,
                         cudaFuncAttributeMaxDynamicSharedMemorySize, ATT_SMEM);
    attn_mma_kernel<<<dim3(T_ / 128, NH_), 256, ATT_SMEM>>>();

    // 5) out = att @ o_w^T  (fp16 2-pass HMMA)
    gemm_fp16x2_kernel<<<dim3(HS_ / BN, T_ / BM), 128, GEMM_SMEM>>>(
        ath, atl, wo, nullptr, out, HS_, HS_);
}

// round 9
// speedup vs baseline: 2.6383x; 1.5927x over previous
#include <cuda_runtime.h>
#include <cuda_fp16.h>
#include <cstdint>
#include <math.h>

#define T_   2048
#define HS_  4096
#define NH_  32
#define NKV_ 8
#define HD_  128
#define QKVN_ ((NH_ + 2*NKV_)*HD_)   // 6144

// ======================= helpers ===========================================
__device__ __forceinline__ uint32_t smem_to_u32(const void* smem_ptr) {
    uint32_t addr;
    asm("{ .reg .u64 tmp; cvta.to.shared.u64 tmp, %1; cvt.u32.u64 %0, tmp; }"
        : "=r"(addr) : "l"(smem_ptr));
    return addr;
}
__device__ __forceinline__ void ldsm_x4(uint32_t addr, uint32_t* r) {
    asm volatile("ldmatrix.sync.aligned.m8n8.x4.shared.b16 {%0,%1,%2,%3}, [%4];"
        : "=r"(r[0]), "=r"(r[1]), "=r"(r[2]), "=r"(r[3]) : "r"(addr));
}
__device__ __forceinline__ void ldsm_x4_trans(uint32_t addr, uint32_t* r) {
    asm volatile("ldmatrix.sync.aligned.m8n8.x4.trans.shared.b16 {%0,%1,%2,%3}, [%4];"
        : "=r"(r[0]), "=r"(r[1]), "=r"(r[2]), "=r"(r[3]) : "r"(addr));
}
__device__ __forceinline__ void mma16816(float* d, const uint32_t* a,
                                         const uint32_t b0, const uint32_t b1) {
    asm volatile("mma.sync.aligned.m16n8k16.row.col.f32.f16.f16.f32 "
        "{%0,%1,%2,%3}, {%4,%5,%6,%7}, {%8,%9}, {%0,%1,%2,%3};"
        : "+f"(d[0]), "+f"(d[1]), "+f"(d[2]), "+f"(d[3])
        : "r"(a[0]), "r"(a[1]), "r"(a[2]), "r"(a[3]), "r"(b0), "r"(b1));
}
__device__ __forceinline__ uint32_t packh(float a, float b) {
    __half2 t = __floats2half2_rn(a, b);
    return *reinterpret_cast<uint32_t*>(&t);
}
__device__ __forceinline__ void split2h(float a, float b,
                                        uint32_t& hi, uint32_t& lo) {
    __half ha = __float2half_rn(a), hb = __float2half_rn(b);
    hi = packh(__half2float(ha), __half2float(hb));
    lo = packh(a - __half2float(ha), b - __half2float(hb));
}

// ======================= scratch (device globals) ===========================
__device__ __align__(256) __half g_xn [T_*HS_];
__device__ __align__(256) __half g_wq [QKVN_*HS_];
__device__ __align__(256) __half g_wo [HS_*HS_];
__device__ __align__(256) __half g_att[T_*HS_];
__device__ float g_qkv[T_*QKVN_];
__device__ __align__(256) __half g_qh[NH_ *T_*HD_];
__device__ __align__(256) __half g_ql[NH_ *T_*HD_];
__device__ __align__(256) __half g_k [NKV_*T_*HD_];
__device__ __align__(256) __half g_v [NKV_*T_*HD_];

// ======================= kernel: fp32 -> fp16 ================================
__global__ void cvt_half_kernel(const float* __restrict__ x,
                                __half* __restrict__ h, int n) {
    int i = (blockIdx.x * blockDim.x + threadIdx.x) * 4;
    if (i >= n) return;
    float4 v = *(const float4*)(x + i);
    __half2* hp = (__half2*)(h + i);
    hp[0] = __floats2half2_rn(v.x, v.y);
    hp[1] = __floats2half2_rn(v.z, v.w);
}

// ======================= kernel: RMSNorm(hidden) -> fp16 ====================
__global__ void rmsnorm_x_kernel(const float* __restrict__ x,
                                 const float* __restrict__ w) {
    int row = blockIdx.x;
    const float* xr = x + (size_t)row * HS_;
    float ss = 0.f;
    for (int i = threadIdx.x; i < HS_; i += blockDim.x) {
        float v = xr[i];
        ss += v * v;
    }
    for (int off = 16; off; off >>= 1)
        ss += __shfl_xor_sync(0xffffffffu, ss, off);
    __shared__ float wr[8];
    int lane = threadIdx.x & 31, wid = threadIdx.x >> 5;
    if (lane == 0) wr[wid] = ss;
    __syncthreads();
    float tot = 0.f;
#pragma unroll
    for (int i = 0; i < 8; i++) tot += wr[i];
    float inv = rsqrtf(tot / (float)HS_ + 1e-6f);
    for (int i = threadIdx.x; i < HS_; i += blockDim.x) {
        float v = xr[i] * inv * w[i];
        g_xn[(size_t)row * HS_ + i] = __float2half_rn(v);
    }
}

// ======================= fp16 single-pass GEMM: C = A*B^T (+bias) ===========
// 128 threads, 4 warps (2x2), CTA 128x128, warp tile 64x64,
// 4-stage pipeline, 2 CTAs/SM.
#define BM 128
#define BN 128
#define BK 32
#define ROWB 80                  // bytes per smem row: 40 fp16 (pad 32->40)
#define A_ARR (128 * ROWB)       // 10240 per array
#define B_OFF  A_ARR
#define STG  (2 * A_ARR)         // 20480 bytes per stage
#define NSTAGE 4
#define GEMM_SMEM (NSTAGE * STG) // 81920 -> 2 CTAs/SM

__device__ __forceinline__ void gemm_load_stage(
    uint32_t sb, int stage,
    const __half* __restrict__ A, const __half* __restrict__ B,
    int bm, int bn, int k0, int K, int tid)
{
    uint32_t base = sb + stage * STG;
    // 2 arrays x 128 rows x 4 chunks(16B) = 1024 chunks; 8 per thread
#pragma unroll
    for (int ii = 0; ii < 8; ii++) {
        int s = tid + ii * 128;
        int arr = s >> 9;                // 0=A 1=B
        int r = (s >> 2) & 127, c = s & 3;
        const __half* srcb = arr ? B : A;
        int grow = (arr ? bn : bm) + r;
        const __half* src = srcb + (size_t)grow * K + k0 + c * 8;
        uint32_t dst = base + arr * A_ARR + r * ROWB + c * 16;
        asm volatile("cp.async.cg.shared.global [%0], [%1], 16;"
                     :: "r"(dst), "l"(src));
    }
    asm volatile("cp.async.commit_group;" ::: "memory");
}

__global__ void __launch_bounds__(128, 2)
gemm_fp16_kernel(const __half* __restrict__ A,
                 const __half* __restrict__ B,
                 const float* __restrict__ bias,
                 float* __restrict__ C, int N, int K)
{
    extern __shared__ char smem[];
    uint32_t sb = smem_to_u32(smem);
    int tid = threadIdx.x, lane = tid & 31, wid = tid >> 5;
    int wm = wid >> 1, wn = wid & 1;       // warp grid 2 x 2
    int bm = blockIdx.y * BM, bn = blockIdx.x * BN;
    int nk = K / BK;

    float acc[4][8][4];
#pragma unroll
    for (int i = 0; i < 4; i++)
#pragma unroll
        for (int j = 0; j < 8; j++)
#pragma unroll
            for (int c = 0; c < 4; c++) acc[i][j][c] = 0.f;

    gemm_load_stage(sb, 0, A, B, bm, bn, 0,      K, tid);
    gemm_load_stage(sb, 1, A, B, bm, bn, BK,     K, tid);
    gemm_load_stage(sb, 2, A, B, bm, bn, 2 * BK, K, tid);
    gemm_load_stage(sb, 3, A, B, bm, bn, 3 * BK, K, tid);

    int a_r = (lane & 15);
    int a_c8 = (lane >> 4) << 3;
    int b_r = (lane & 7) + ((lane & 16) >> 1);
    int b_c8 = (lane & 8);

    for (int it = 0; it < nk; it++) {
        asm volatile("cp.async.wait_group 3;" ::: "memory");
        __syncthreads();

        uint32_t base = sb + (it % NSTAGE) * STG;

#pragma unroll
        for (int ks = 0; ks < BK; ks += 16) {
            int acolB = (ks + a_c8) * 2;
            int bcolB = (ks + b_c8) * 2;
            uint32_t bh[4][4];
#pragma unroll
            for (int g = 0; g < 4; g++) {
                uint32_t ro = (uint32_t)((wn * 64 + g * 16 + b_r) * ROWB) + bcolB;
                ldsm_x4(base + B_OFF + ro, bh[g]);
            }
#pragma unroll
            for (int mi = 0; mi < 4; mi++) {
                uint32_t ah[4];
                uint32_t ro = (uint32_t)((wm * 64 + mi * 16 + a_r) * ROWB) + acolB;
                ldsm_x4(base + ro, ah);
#pragma unroll
                for (int g = 0; g < 4; g++) {
                    mma16816(acc[mi][2*g],   ah, bh[g][0], bh[g][1]);
                    mma16816(acc[mi][2*g+1], ah, bh[g][2], bh[g][3]);
                }
            }
        }
        __syncthreads();
        if (it + NSTAGE < nk)
            gemm_load_stage(sb, it % NSTAGE, A, B, bm, bn,
                            (it + NSTAGE) * BK, K, tid);
    }

#pragma unroll
    for (int mi = 0; mi < 4; mi++) {
#pragma unroll
        for (int j = 0; j < 8; j++) {
            int r0 = bm + wm * 64 + mi * 16 + (lane >> 2);
            int c0 = bn + wn * 64 + j * 8 + 2 * (lane & 3);
            float b0 = 0.f, b1 = 0.f;
            if (bias) { b0 = bias[c0]; b1 = bias[c0 + 1]; }
            float2 v0 = make_float2(acc[mi][j][0] + b0, acc[mi][j][1] + b1);
            float2 v1 = make_float2(acc[mi][j][2] + b0, acc[mi][j][3] + b1);
            *(float2*)(C + (size_t)r0 * N + c0) = v0;
            *(float2*)(C + (size_t)(r0 + 8) * N + c0) = v1;
        }
    }
}

// ======================= kernel: per-head RMSNorm + RoPE ====================
__global__ void qk_rope_kernel(const int* __restrict__ positions,
                               const float* __restrict__ qw,
                               const float* __restrict__ kw) {
    int t = blockIdx.x;
    int head = blockIdx.y;
    int i = threadIdx.x;   // 0..127
    float v = g_qkv[(size_t)t * QKVN_ + head * HD_ + i];

    if (head >= NH_ + NKV_) {   // v heads: single fp16 [KV,T,D]
        size_t idx = ((size_t)(head - NH_ - NKV_) * T_ + t) * HD_ + i;
        g_v[idx] = __float2half_rn(v);
        return;
    }

    float ss = v * v;
    for (int off = 16; off; off >>= 1)
        ss += __shfl_xor_sync(0xffffffffu, ss, off);
    __shared__ float wr[4];
    __shared__ float buf[HD_];
    int lane = i & 31, wid = i >> 5;
    if (lane == 0) wr[wid] = ss;
    __syncthreads();
    float tot = wr[0] + wr[1] + wr[2] + wr[3];
    float inv = rsqrtf(tot / (float)HD_ + 1e-6f);
    const float* w = (head < NH_) ? qw : kw;
    float nv = v * inv * w[i];
    buf[i] = nv;
    __syncthreads();

    int fi = i & 63;
    float invf = 1.0f / powf(10000.0f, (float)fi * (1.0f / 64.0f));
    float ang = (float)positions[t] * invf;
    float s, c;
    sincosf(ang, &s, &c);
    float other = buf[i ^ 64];
    float out = (i < 64) ? (nv * c - other * s) : (nv * c + other * s);

    if (head < NH_) {
        float sc = out * 0.08838834764831845f;   // fold in softmax scale
        size_t idx = ((size_t)head * T_ + t) * HD_ + i;
        __half h = __float2half_rn(sc);
        g_qh[idx] = h;
        g_ql[idx] = __float2half_rn(sc - __half2float(h));
    } else {
        size_t idx = ((size_t)(head - NH_) * T_ + t) * HD_ + i;
        g_k[idx] = __float2half_rn(out);
    }
}

// ======================= tensor-core flash attention (fp16 2-pass) ==========
#define ASTR 272                    // smem row stride bytes (136 fp16)
#define AQSZ (128 * ASTR)           // 34816: one Q array (128 rows)
#define AKSZ (64 * ASTR)            // 17408: one K or V array (64 rows)
#define ASTAGE (2 * AKSZ)           // 34816: K,V
#define ATT_SMEM (2 * AQSZ + 2 * ASTAGE)   // 139264

__device__ __forceinline__ void attn_load_kv(
    uint32_t sb, int buf,
    const __half* K, const __half* V,
    int kt0, int tid)
{
    uint32_t base = sb + 2 * AQSZ + buf * ASTAGE;
#pragma unroll
    for (int ii = 0; ii < 8; ii++) {
        int s = tid + ii * 256;
        int arr = s >> 10;          // 0=K 1=V
        int r = (s >> 4) & 63;
        int c = s & 15;
        const __half* src = (arr ? V : K) + (size_t)(kt0 + r) * HD_ + c * 8;
        uint32_t dst = base + arr * AKSZ + r * ASTR + c * 16;
        asm volatile("cp.async.cg.shared.global [%0], [%1], 16;"
                     :: "r"(dst), "l"(src));
    }
    asm volatile("cp.async.commit_group;" ::: "memory");
}

__global__ void __launch_bounds__(256, 1) attn_mma_kernel() {
    extern __shared__ char smc[];
    uint32_t sb = smem_to_u32(smc);
    int qb = 15 - blockIdx.x;            // reversed: big workloads first
    int h  = blockIdx.y;
    int kvh = h >> 2;
    int tid = threadIdx.x, lane = tid & 31, wid = tid >> 5;

    const __half* Qhg = g_qh + ((size_t)h * T_ + qb * 128) * HD_;
    const __half* Qlg = g_ql + ((size_t)h * T_ + qb * 128) * HD_;
    const __half* Kg  = g_k  + (size_t)kvh * T_ * HD_;
    const __half* Vg  = g_v  + (size_t)kvh * T_ * HD_;

    // Q load
#pragma unroll
    for (int ii = 0; ii < 16; ii++) {
        int s = tid + ii * 256;
        int arr = s >> 11;              // 0 = hi, 1 = lo
        int r = (s >> 4) & 127;
        int c = s & 15;
        const __half* src = (arr ? Qlg : Qhg) + (size_t)r * HD_ + c * 8;
        uint32_t dst = sb + arr * AQSZ + r * ASTR + c * 16;
        asm volatile("cp.async.cg.shared.global [%0], [%1], 16;"
                     :: "r"(dst), "l"(src));
    }
    asm volatile("cp.async.commit_group;" ::: "memory");

    int nkt = 2 * qb + 2;
    attn_load_kv(sb, 0, Kg, Vg, 0,  tid);
    attn_load_kv(sb, 1, Kg, Vg, 64, tid);

    asm volatile("cp.async.wait_group 2;" ::: "memory");   // Q done
    __syncthreads();

    // extract Q fragments to registers
    int a_r = lane & 15, a_c8 = (lane >> 4) << 3;
    uint32_t qhf[8][4], qlf[8][4];
    {
        uint32_t qrow = (uint32_t)((wid * 16 + a_r) * ASTR);
#pragma unroll
        for (int j = 0; j < 8; j++) {
            uint32_t co = (uint32_t)((j * 16 + a_c8) * 2);
            ldsm_x4(sb + qrow + co, qhf[j]);
            ldsm_x4(sb + AQSZ + qrow + co, qlf[j]);
        }
    }

    float o[16][4];
#pragma unroll
    for (int j = 0; j < 16; j++)
#pragma unroll
        for (int c = 0; c < 4; c++) o[j][c] = 0.f;
    float mA = -1e30f, mB = -1e30f, lA = 0.f, lB = 0.f;

    int b_r = (lane & 7) + ((lane & 16) >> 1);   // K frag row map
    int b_c8 = (lane & 8);
    int v_r = (lane & 7) + 8 * ((lane >> 3) & 1);  // V trans frag row map
    int v_c8 = (lane >> 4) * 8;

    int wrow = qb * 128 + wid * 16;              // warp's first q row

    for (int kb = 0; kb < nkt; kb++) {
        asm volatile("cp.async.wait_group 1;" ::: "memory");
        __syncthreads();

        int kbase = kb * 64;
        bool active = (kbase <= wrow + 15);      // any unmasked element?
        uint32_t st = sb + 2 * AQSZ + (kb & 1) * ASTAGE;

        if (active) {
            // ---- S = Q K^T (Q split x2, K single) ----
            float s[8][4];
#pragma unroll
            for (int t = 0; t < 8; t++)
#pragma unroll
                for (int c = 0; c < 4; c++) s[t][c] = 0.f;

#pragma unroll
            for (int j = 0; j < 8; j++) {        // k16 over D
                uint32_t colB = (uint32_t)((j * 16 + b_c8) * 2);
#pragma unroll
                for (int g = 0; g < 4; g++) {    // n16 over 64 tokens
                    uint32_t kh[4];
                    uint32_t ro = st + (uint32_t)((g * 16 + b_r) * ASTR) + colB;
                    ldsm_x4(ro, kh);
                    mma16816(s[2*g],   qhf[j], kh[0], kh[1]);
                    mma16816(s[2*g],   qlf[j], kh[0], kh[1]);
                    mma16816(s[2*g+1], qhf[j], kh[2], kh[3]);
                    mma16816(s[2*g+1], qlf[j], kh[2], kh[3]);
                }
            }

            // ---- causal mask (diagonal tiles only) ----
            if (kbase + 63 > wrow) {
                int rA = wrow + (lane >> 2), rB = rA + 8;
#pragma unroll
                for (int t = 0; t < 8; t++) {
                    int c0 = kbase + t * 8 + 2 * (lane & 3);
                    if (c0     > rA) s[t][0] = -1e30f;
                    if (c0 + 1 > rA) s[t][1] = -1e30f;
                    if (c0     > rB) s[t][2] = -1e30f;
                    if (c0 + 1 > rB) s[t][3] = -1e30f;
                }
            }

            // ---- online softmax ----
            float rmA = -1e30f, rmB = -1e30f;
#pragma unroll
            for (int t = 0; t < 8; t++) {
                rmA = fmaxf(rmA, fmaxf(s[t][0], s[t][1]));
                rmB = fmaxf(rmB, fmaxf(s[t][2], s[t][3]));
            }
            rmA = fmaxf(rmA, __shfl_xor_sync(0xffffffffu, rmA, 1));
            rmA = fmaxf(rmA, __shfl_xor_sync(0xffffffffu, rmA, 2));
            rmB = fmaxf(rmB, __shfl_xor_sync(0xffffffffu, rmB, 1));
            rmB = fmaxf(rmB, __shfl_xor_sync(0xffffffffu, rmB, 2));
            float mnA = fmaxf(mA, rmA), mnB = fmaxf(mB, rmB);
            float aA = __expf(mA - mnA), aB = __expf(mB - mnB);
            mA = mnA; mB = mnB;

            float rsA = 0.f, rsB = 0.f;
#pragma unroll
            for (int t = 0; t < 8; t++) {
                s[t][0] = __expf(s[t][0] - mnA);
                s[t][1] = __expf(s[t][1] - mnA);
                s[t][2] = __expf(s[t][2] - mnB);
                s[t][3] = __expf(s[t][3] - mnB);
                rsA += s[t][0] + s[t][1];
                rsB += s[t][2] + s[t][3];
            }
            rsA += __shfl_xor_sync(0xffffffffu, rsA, 1);
            rsA += __shfl_xor_sync(0xffffffffu, rsA, 2);
            rsB += __shfl_xor_sync(0xffffffffu, rsB, 1);
            rsB += __shfl_xor_sync(0xffffffffu, rsB, 2);
            lA = lA * aA + rsA;
            lB = lB * aB + rsB;
#pragma unroll
            for (int j = 0; j < 16; j++) {
                o[j][0] *= aA; o[j][1] *= aA;
                o[j][2] *= aB; o[j][3] *= aB;
            }

            // ---- O += P V (P split x2, V single) ----
#pragma unroll
            for (int t = 0; t < 4; t++) {        // k16 over 64 tokens
                uint32_t pah[4], pal[4];
                split2h(s[2*t][0],   s[2*t][1],   pah[0], pal[0]);
                split2h(s[2*t][2],   s[2*t][3],   pah[1], pal[1]);
                split2h(s[2*t+1][0], s[2*t+1][1], pah[2], pal[2]);
                split2h(s[2*t+1][2], s[2*t+1][3], pah[3], pal[3]);
                uint32_t vrow = st + AKSZ
                              + (uint32_t)((t * 16 + v_r) * ASTR);
#pragma unroll
                for (int g = 0; g < 8; g++) {    // n16 over D
                    uint32_t vh[4];
                    uint32_t vo = vrow + (uint32_t)((g * 16 + v_c8) * 2);
                    ldsm_x4_trans(vo, vh);
                    mma16816(o[2*g],   pah, vh[0], vh[1]);
                    mma16816(o[2*g],   pal, vh[0], vh[1]);
                    mma16816(o[2*g+1], pah, vh[2], vh[3]);
                    mma16816(o[2*g+1], pal, vh[2], vh[3]);
                }
            }
        }

        __syncthreads();
        if (kb + 2 < nkt)
            attn_load_kv(sb, kb & 1, Kg, Vg, (kb + 2) * 64, tid);
    }

    // ---- epilogue: normalize, write single fp16 ----
    float ilA = 1.f / lA, ilB = 1.f / lB;
    int rowA = wrow + (lane >> 2);
#pragma unroll
    for (int j = 0; j < 16; j++) {
        int col = h * HD_ + j * 8 + 2 * (lane & 3);
        *(uint32_t*)(g_att + (size_t)rowA * HS_ + col) =
            packh(o[j][0] * ilA, o[j][1] * ilA);
        *(uint32_t*)(g_att + (size_t)(rowA + 8) * HS_ + col) =
            packh(o[j][2] * ilB, o[j][3] * ilB);
    }
}

// ======================= launcher ===========================================
extern "C" void kernel_launch(void* const* d_in, const int* in_sizes, int n_in,
                              void* d_out, int out_size) {
    const int*   positions = (const int*)d_in[0];
    const float* hidden    = (const float*)d_in[1];
    const float* ln_w      = (const float*)d_in[2];
    const float* qkv_w     = (const float*)d_in[3];
    const float* qkv_b     = (const float*)d_in[4];
    const float* qn_w      = (const float*)d_in[5];
    const float* kn_w      = (const float*)d_in[6];
    const float* o_w       = (const float*)d_in[7];
    float* out = (float*)d_out;

    void* p;
    cudaGetSymbolAddress(&p, g_xn);   __half* xn  = (__half*)p;
    cudaGetSymbolAddress(&p, g_wq);   __half* wq  = (__half*)p;
    cudaGetSymbolAddress(&p, g_wo);   __half* wo  = (__half*)p;
    cudaGetSymbolAddress(&p, g_att);  __half* att = (__half*)p;
    cudaGetSymbolAddress(&p, g_qkv);  float* qkv = (float*)p;

    // weight conversion (single fp16)
    {
        int n1 = QKVN_ * HS_;
        cvt_half_kernel<<<n1 / 4 / 256, 256>>>(qkv_w, wq, n1);
        int n2 = HS_ * HS_;
        cvt_half_kernel<<<n2 / 4 / 256, 256>>>(o_w, wo, n2);
    }

    // 1) RMSNorm(hidden) -> fp16
    rmsnorm_x_kernel<<<T_, 256>>>(hidden, ln_w);

    // 2) qkv = xn @ qkv_w^T + bias   (fp16 single-pass HMMA, 4-stage)
    cudaFuncSetAttribute(gemm_fp16_kernel,
                         cudaFuncAttributeMaxDynamicSharedMemorySize, GEMM_SMEM);
    gemm_fp16_kernel<<<dim3(QKVN_ / BN, T_ / BM), 128, GEMM_SMEM>>>(
        xn, wq, qkv_b, qkv, QKVN_, HS_);

    // 3) q/k RMSNorm + RoPE (scale folded into q; q split, k/v single fp16)
    qk_rope_kernel<<<dim3(T_, NH_ + 2 * NKV_), 128>>>(positions, qn_w, kn_w);

    // 4) causal attention (fp16, Q/P split)
    cudaFuncSetAttribute(attn_mma_kernel,
                         cudaFuncAttributeMaxDynamicSharedMemorySize, ATT_SMEM);
    attn_mma_kernel<<<dim3(T_ / 128, NH_), 256, ATT_SMEM>>>();

    // 5) out = att @ o_w^T  (fp16 single-pass HMMA)
    gemm_fp16_kernel<<<dim3(HS_ / BN, T_ / BM), 128, GEMM_SMEM>>>(
        att, wo, nullptr, out, HS_, HS_);
}